// round 1
// baseline (speedup 1.0000x reference)
#include <cuda_runtime.h>

#define E_TOTAL   524288
#define N_AG      16384
#define TILE_E    32
#define NTHREADS  256
#define AGG_STRIDE 66   // 64 MLP feats + 2 barrier components

// Scratch for per-agent aggregation (alloc-free rule: static __device__)
__device__ float g_agg[N_AG * AGG_STRIDE];

// ---------------- packed f32x2 helpers (FFMA2 path) ----------------
__device__ __forceinline__ unsigned long long dup2(float a) {
    unsigned long long r;
    asm("mov.b64 %0, {%1, %1};" : "=l"(r) : "f"(a));
    return r;
}
__device__ __forceinline__ unsigned long long pack2(float lo, float hi) {
    unsigned long long r;
    asm("mov.b64 %0, {%1, %2};" : "=l"(r) : "f"(lo), "f"(hi));
    return r;
}
__device__ __forceinline__ void unpack2(unsigned long long v, float& lo, float& hi) {
    asm("mov.b64 {%0, %1}, %2;" : "=f"(lo), "=f"(hi) : "l"(v));
}
__device__ __forceinline__ void fma2(unsigned long long& acc, unsigned long long a, unsigned long long b) {
    asm("fma.rn.f32x2 %0, %1, %2, %0;" : "+l"(acc) : "l"(a), "l"(b));
}

// smem float offsets (edge kernel)
//   sX   [32][4]        128
//   h1   [256][33]     8448   (k-major, padded: conflict-free column reads)
//   h2   [256][33]     8448
//   wc   [32][256]     8192   (streamed weight chunk)
//   h3   [32][66]      2112
//   sseg [32] ints
#define EDGE_SMEM_FLOATS (128 + 8448 + 8448 + 8192 + 2112)
#define EDGE_SMEM_BYTES  (EDGE_SMEM_FLOATS * 4 + 32 * 4)

__global__ void __launch_bounds__(NTHREADS, 2) edge_kernel(
    const float* __restrict__ ef, const int* __restrict__ seg,
    const float* __restrict__ Wp1, const float* __restrict__ bp1,
    const float* __restrict__ Wp2, const float* __restrict__ bp2,
    const float* __restrict__ Wp3, const float* __restrict__ bp3)
{
    extern __shared__ float sm[];
    float* sX = sm;                    // 128
    float* h1 = sm + 128;              // 8448
    float* h2 = h1 + 8448;             // 8448
    float* wc = h2 + 8448;             // 8192
    float* h3 = wc + 8192;             // 2112
    int*  sseg = (int*)(h3 + 2112);    // 32 ints

    const int tid = threadIdx.x;
    const int e0  = blockIdx.x * TILE_E;

    if (tid < 128) sX[tid] = ef[e0 * 4 + tid];
    if (tid < 32)  sseg[tid] = seg[e0 + tid];
    __syncthreads();

    // ---- layer 1: h1 = relu(X @ Wp1 + bp1), j = tid ----
    {
        const float w0 = Wp1[0 * 256 + tid];
        const float w1 = Wp1[1 * 256 + tid];
        const float w2 = Wp1[2 * 256 + tid];
        const float w3 = Wp1[3 * 256 + tid];
        const float b  = bp1[tid];
        #pragma unroll 8
        for (int e = 0; e < 32; e++) {
            float v = b + sX[e*4+0]*w0 + sX[e*4+1]*w1 + sX[e*4+2]*w2 + sX[e*4+3]*w3;
            h1[tid * 33 + e] = fmaxf(v, 0.0f);   // k-major store
        }
    }
    __syncthreads();

    const int te = tid & 7;        // edge group (4 edges each)
    const int tn = tid >> 3;       // 0..31 column group (8 cols each)
    const int el = te * 4;
    const int n0 = tn * 8;

    // ---- layer 2: h2 = relu(h1 @ Wp2 + bp2), thread tile 4e x 8n ----
    unsigned long long acc[4][4];
    {
        const float4 blo = *(const float4*)&bp2[n0];
        const float4 bhi = *(const float4*)&bp2[n0 + 4];
        const unsigned long long p0 = pack2(blo.x, blo.y), p1 = pack2(blo.z, blo.w);
        const unsigned long long p2 = pack2(bhi.x, bhi.y), p3 = pack2(bhi.z, bhi.w);
        #pragma unroll
        for (int i = 0; i < 4; i++) { acc[i][0]=p0; acc[i][1]=p1; acc[i][2]=p2; acc[i][3]=p3; }

        for (int kc = 0; kc < 8; kc++) {
            __syncthreads();
            const float4* src = (const float4*)(Wp2 + kc * 32 * 256);
            float4* dst = (float4*)wc;
            #pragma unroll
            for (int i = 0; i < 8; i++) dst[tid + i * 256] = src[tid + i * 256];
            __syncthreads();
            #pragma unroll
            for (int k = 0; k < 32; k++) {
                const float* hrow = &h1[(kc * 32 + k) * 33 + el];
                const unsigned long long a0 = dup2(hrow[0]);
                const unsigned long long a1 = dup2(hrow[1]);
                const unsigned long long a2 = dup2(hrow[2]);
                const unsigned long long a3 = dup2(hrow[3]);
                const ulonglong2 q0 = *(const ulonglong2*)&wc[k * 256 + n0];
                const ulonglong2 q1 = *(const ulonglong2*)&wc[k * 256 + n0 + 4];
                fma2(acc[0][0], a0, q0.x); fma2(acc[0][1], a0, q0.y);
                fma2(acc[0][2], a0, q1.x); fma2(acc[0][3], a0, q1.y);
                fma2(acc[1][0], a1, q0.x); fma2(acc[1][1], a1, q0.y);
                fma2(acc[1][2], a1, q1.x); fma2(acc[1][3], a1, q1.y);
                fma2(acc[2][0], a2, q0.x); fma2(acc[2][1], a2, q0.y);
                fma2(acc[2][2], a2, q1.x); fma2(acc[2][3], a2, q1.y);
                fma2(acc[3][0], a3, q0.x); fma2(acc[3][1], a3, q0.y);
                fma2(acc[3][2], a3, q1.x); fma2(acc[3][3], a3, q1.y);
            }
        }
        #pragma unroll
        for (int i = 0; i < 4; i++) {
            #pragma unroll
            for (int j = 0; j < 4; j++) {
                float lo, hi; unpack2(acc[i][j], lo, hi);
                h2[(n0 + 2*j    ) * 33 + el + i] = fmaxf(lo, 0.0f);
                h2[(n0 + 2*j + 1) * 33 + el + i] = fmaxf(hi, 0.0f);
            }
        }
    }

    // ---- layer 3: h3 = h2 @ Wp3 + bp3, thread tile 4e x 2n ----
    {
        const int c0 = tn * 2;     // 0..62
        unsigned long long acc3[4];
        const unsigned long long binit = pack2(bp3[c0], bp3[c0 + 1]);
        #pragma unroll
        for (int i = 0; i < 4; i++) acc3[i] = binit;

        for (int kc = 0; kc < 8; kc++) {
            __syncthreads();
            const float4* src = (const float4*)(Wp3 + kc * 32 * 64);
            float4* dst = (float4*)wc;
            dst[tid]       = src[tid];
            dst[tid + 256] = src[tid + 256];
            __syncthreads();
            #pragma unroll
            for (int k = 0; k < 32; k++) {
                const float* hrow = &h2[(kc * 32 + k) * 33 + el];
                const unsigned long long b = *(const unsigned long long*)&wc[k * 64 + c0];
                fma2(acc3[0], dup2(hrow[0]), b);
                fma2(acc3[1], dup2(hrow[1]), b);
                fma2(acc3[2], dup2(hrow[2]), b);
                fma2(acc3[3], dup2(hrow[3]), b);
            }
        }
        #pragma unroll
        for (int i = 0; i < 4; i++) {
            float lo, hi; unpack2(acc3[i], lo, hi);
            h3[(el + i) * 66 + c0]     = lo;
            h3[(el + i) * 66 + c0 + 1] = hi;
        }
    }

    // ---- analytic barrier per edge ----
    if (tid < 32) {
        const float px = sX[tid * 4 + 0];
        const float py = sX[tid * 4 + 1];
        const float d  = sqrtf(px * px + py * py);
        const float s  = -1.0f / (d * (d - (float)(1.2 * 0.15)));
        h3[tid * 66 + 64] = px * s;
        h3[tid * 66 + 65] = py * s;
    }
    __syncthreads();

    // ---- segmented reduce (ids sorted) -> global atomics ----
    if (tid < 66) {
        int cur = sseg[0];
        float run = 0.0f;
        #pragma unroll 1
        for (int e = 0; e < 32; e++) {
            const int s = sseg[e];
            if (s != cur) { atomicAdd(&g_agg[cur * 66 + tid], run); run = 0.0f; cur = s; }
            run += h3[e * 66 + tid];
        }
        atomicAdd(&g_agg[cur * 66 + tid], run);
    }
}

__global__ void zero_kernel() {
    const int i = blockIdx.x * blockDim.x + threadIdx.x;
    if (i < N_AG * AGG_STRIDE) g_agg[i] = 0.0f;
}

// agent kernel smem: g1[64][33]=2112, h2[256][33]=8448, r2[256][33]=8448,
//                    wc[32][256]=8192, w3[512]
#define AGENT_SMEM_FLOATS (2112 + 8448 + 8448 + 8192 + 512)
#define AGENT_SMEM_BYTES  (AGENT_SMEM_FLOATS * 4)

__global__ void __launch_bounds__(NTHREADS, 2) agent_kernel(
    const float* __restrict__ Wr1, const float* __restrict__ br1,
    const float* __restrict__ Wr2, const float* __restrict__ br2,
    const float* __restrict__ Wr3, const float* __restrict__ br3,
    float* __restrict__ out)
{
    extern __shared__ float sm[];
    float* g1 = sm;                 // 2112
    float* h2 = g1 + 2112;          // 8448
    float* r2 = h2 + 8448;          // 8448
    float* wc = r2 + 8448;          // 8192
    float* w3 = wc + 8192;          // 512

    const int tid = threadIdx.x;
    const int a0  = blockIdx.x * 32;

    // load agg tile k-major: g1[k][e]
    #pragma unroll
    for (int i = 0; i < 8; i++) {
        const int idx = tid + i * 256;      // 0..2047
        const int e = idx >> 6, k = idx & 63;
        g1[k * 33 + e] = g_agg[(a0 + e) * 66 + k];
    }
    w3[tid]       = Wr3[tid];
    w3[tid + 256] = Wr3[tid + 256];
    __syncthreads();

    const int te = tid & 7;
    const int tn = tid >> 3;
    const int el = te * 4;
    const int n0 = tn * 8;

    unsigned long long acc[4][4];

    // ---- r1 = relu(agg @ Wr1 + br1), K=64 ----
    {
        const float4 blo = *(const float4*)&br1[n0];
        const float4 bhi = *(const float4*)&br1[n0 + 4];
        const unsigned long long p0 = pack2(blo.x, blo.y), p1 = pack2(blo.z, blo.w);
        const unsigned long long p2 = pack2(bhi.x, bhi.y), p3 = pack2(bhi.z, bhi.w);
        #pragma unroll
        for (int i = 0; i < 4; i++) { acc[i][0]=p0; acc[i][1]=p1; acc[i][2]=p2; acc[i][3]=p3; }

        for (int kc = 0; kc < 2; kc++) {
            __syncthreads();
            const float4* src = (const float4*)(Wr1 + kc * 32 * 256);
            float4* dst = (float4*)wc;
            #pragma unroll
            for (int i = 0; i < 8; i++) dst[tid + i * 256] = src[tid + i * 256];
            __syncthreads();
            #pragma unroll
            for (int k = 0; k < 32; k++) {
                const float* hrow = &g1[(kc * 32 + k) * 33 + el];
                const unsigned long long a0d = dup2(hrow[0]);
                const unsigned long long a1d = dup2(hrow[1]);
                const unsigned long long a2d = dup2(hrow[2]);
                const unsigned long long a3d = dup2(hrow[3]);
                const ulonglong2 q0 = *(const ulonglong2*)&wc[k * 256 + n0];
                const ulonglong2 q1 = *(const ulonglong2*)&wc[k * 256 + n0 + 4];
                fma2(acc[0][0], a0d, q0.x); fma2(acc[0][1], a0d, q0.y);
                fma2(acc[0][2], a0d, q1.x); fma2(acc[0][3], a0d, q1.y);
                fma2(acc[1][0], a1d, q0.x); fma2(acc[1][1], a1d, q0.y);
                fma2(acc[1][2], a1d, q1.x); fma2(acc[1][3], a1d, q1.y);
                fma2(acc[2][0], a2d, q0.x); fma2(acc[2][1], a2d, q0.y);
                fma2(acc[2][2], a2d, q1.x); fma2(acc[2][3], a2d, q1.y);
                fma2(acc[3][0], a3d, q0.x); fma2(acc[3][1], a3d, q0.y);
                fma2(acc[3][2], a3d, q1.x); fma2(acc[3][3], a3d, q1.y);
            }
        }
        #pragma unroll
        for (int i = 0; i < 4; i++)
            #pragma unroll
            for (int j = 0; j < 4; j++) {
                float lo, hi; unpack2(acc[i][j], lo, hi);
                h2[(n0 + 2*j    ) * 33 + el + i] = fmaxf(lo, 0.0f);
                h2[(n0 + 2*j + 1) * 33 + el + i] = fmaxf(hi, 0.0f);
            }
    }

    // ---- r2 = relu(r1 @ Wr2 + br2), K=256 ----
    {
        const float4 blo = *(const float4*)&br2[n0];
        const float4 bhi = *(const float4*)&br2[n0 + 4];
        const unsigned long long p0 = pack2(blo.x, blo.y), p1 = pack2(blo.z, blo.w);
        const unsigned long long p2 = pack2(bhi.x, bhi.y), p3 = pack2(bhi.z, bhi.w);
        #pragma unroll
        for (int i = 0; i < 4; i++) { acc[i][0]=p0; acc[i][1]=p1; acc[i][2]=p2; acc[i][3]=p3; }

        for (int kc = 0; kc < 8; kc++) {
            __syncthreads();
            const float4* src = (const float4*)(Wr2 + kc * 32 * 256);
            float4* dst = (float4*)wc;
            #pragma unroll
            for (int i = 0; i < 8; i++) dst[tid + i * 256] = src[tid + i * 256];
            __syncthreads();
            #pragma unroll
            for (int k = 0; k < 32; k++) {
                const float* hrow = &h2[(kc * 32 + k) * 33 + el];
                const unsigned long long a0d = dup2(hrow[0]);
                const unsigned long long a1d = dup2(hrow[1]);
                const unsigned long long a2d = dup2(hrow[2]);
                const unsigned long long a3d = dup2(hrow[3]);
                const ulonglong2 q0 = *(const ulonglong2*)&wc[k * 256 + n0];
                const ulonglong2 q1 = *(const ulonglong2*)&wc[k * 256 + n0 + 4];
                fma2(acc[0][0], a0d, q0.x); fma2(acc[0][1], a0d, q0.y);
                fma2(acc[0][2], a0d, q1.x); fma2(acc[0][3], a0d, q1.y);
                fma2(acc[1][0], a1d, q0.x); fma2(acc[1][1], a1d, q0.y);
                fma2(acc[1][2], a1d, q1.x); fma2(acc[1][3], a1d, q1.y);
                fma2(acc[2][0], a2d, q0.x); fma2(acc[2][1], a2d, q0.y);
                fma2(acc[2][2], a2d, q1.x); fma2(acc[2][3], a2d, q1.y);
                fma2(acc[3][0], a3d, q0.x); fma2(acc[3][1], a3d, q0.y);
                fma2(acc[3][2], a3d, q1.x); fma2(acc[3][3], a3d, q1.y);
            }
        }
        #pragma unroll
        for (int i = 0; i < 4; i++)
            #pragma unroll
            for (int j = 0; j < 4; j++) {
                float lo, hi; unpack2(acc[i][j], lo, hi);
                r2[(n0 + 2*j    ) * 33 + el + i] = fmaxf(lo, 0.0f);
                r2[(n0 + 2*j + 1) * 33 + el + i] = fmaxf(hi, 0.0f);
            }
    }
    __syncthreads();

    // ---- final: out = r2 @ Wr3 + br3 + barrier ----
    if (tid < 64) {
        const int e = tid >> 1, c = tid & 1;
        float sum = br3[c];
        #pragma unroll 8
        for (int k = 0; k < 256; k++)
            sum += r2[k * 33 + e] * w3[k * 2 + c];
        out[(a0 + e) * 2 + c] = sum + g_agg[(a0 + e) * 66 + 64 + c];
    }
}

extern "C" void kernel_launch(void* const* d_in, const int* in_sizes, int n_in,
                              void* d_out, int out_size) {
    const float* ef  = (const float*)d_in[0];
    const int*   seg = (const int*)  d_in[1];
    const float* Wp1 = (const float*)d_in[2];
    const float* bp1 = (const float*)d_in[3];
    const float* Wp2 = (const float*)d_in[4];
    const float* bp2 = (const float*)d_in[5];
    const float* Wp3 = (const float*)d_in[6];
    const float* bp3 = (const float*)d_in[7];
    const float* Wr1 = (const float*)d_in[8];
    const float* br1 = (const float*)d_in[9];
    const float* Wr2 = (const float*)d_in[10];
    const float* br2 = (const float*)d_in[11];
    const float* Wr3 = (const float*)d_in[12];
    const float* br3 = (const float*)d_in[13];
    float* out = (float*)d_out;

    cudaFuncSetAttribute(edge_kernel,  cudaFuncAttributeMaxDynamicSharedMemorySize, EDGE_SMEM_BYTES);
    cudaFuncSetAttribute(agent_kernel, cudaFuncAttributeMaxDynamicSharedMemorySize, AGENT_SMEM_BYTES);

    zero_kernel<<<(N_AG * AGG_STRIDE + 255) / 256, 256>>>();
    edge_kernel<<<E_TOTAL / TILE_E, NTHREADS, EDGE_SMEM_BYTES>>>(
        ef, seg, Wp1, bp1, Wp2, bp2, Wp3, bp3);
    agent_kernel<<<N_AG / 32, NTHREADS, AGENT_SMEM_BYTES>>>(
        Wr1, br1, Wr2, br2, Wr3, br3, out);
}

// round 2
// speedup vs baseline: 1.0029x; 1.0029x over previous
#include <cuda_runtime.h>

#define E_TOTAL   524288
#define N_AG      16384
#define TILE_E    32
#define NTHREADS  256
#define AGG_STRIDE 66   // 64 MLP feats + 2 barrier components

// Scratch for per-agent aggregation (alloc-free rule: static __device__)
__device__ float g_agg[N_AG * AGG_STRIDE];

// ---------------- packed f32x2 helpers (FFMA2 path) ----------------
__device__ __forceinline__ unsigned long long dup2(float a) {
    unsigned long long r;
    asm("mov.b64 %0, {%1, %1};" : "=l"(r) : "f"(a));
    return r;
}
__device__ __forceinline__ unsigned long long pack2(float lo, float hi) {
    unsigned long long r;
    asm("mov.b64 %0, {%1, %2};" : "=l"(r) : "f"(lo), "f"(hi));
    return r;
}
__device__ __forceinline__ void unpack2(unsigned long long v, float& lo, float& hi) {
    asm("mov.b64 {%0, %1}, %2;" : "=f"(lo), "=f"(hi) : "l"(v));
}
__device__ __forceinline__ void fma2(unsigned long long& acc, unsigned long long a, unsigned long long b) {
    asm("fma.rn.f32x2 %0, %1, %2, %0;" : "+l"(acc) : "l"(a), "l"(b));
}

// smem float offsets (edge kernel)
//   sX   [32][4]        128
//   h1   [256][33]     8448   (k-major, padded: conflict-free column reads)
//   h2   [256][33]     8448
//   wc   [32][256]     8192   (streamed weight chunk)
//   h3   [32][66]      2112
//   sseg [32] ints
#define EDGE_SMEM_FLOATS (128 + 8448 + 8448 + 8192 + 2112)
#define EDGE_SMEM_BYTES  (EDGE_SMEM_FLOATS * 4 + 32 * 4)

__global__ void __launch_bounds__(NTHREADS, 2) edge_kernel(
    const float* __restrict__ ef, const int* __restrict__ seg,
    const float* __restrict__ Wp1, const float* __restrict__ bp1,
    const float* __restrict__ Wp2, const float* __restrict__ bp2,
    const float* __restrict__ Wp3, const float* __restrict__ bp3)
{
    extern __shared__ float sm[];
    float* sX = sm;                    // 128
    float* h1 = sm + 128;              // 8448
    float* h2 = h1 + 8448;             // 8448
    float* wc = h2 + 8448;             // 8192
    float* h3 = wc + 8192;             // 2112
    int*  sseg = (int*)(h3 + 2112);    // 32 ints

    const int tid = threadIdx.x;
    const int e0  = blockIdx.x * TILE_E;

    if (tid < 128) sX[tid] = ef[e0 * 4 + tid];
    if (tid < 32)  sseg[tid] = seg[e0 + tid];
    __syncthreads();

    // ---- layer 1: h1 = relu(X @ Wp1 + bp1), j = tid ----
    {
        const float w0 = Wp1[0 * 256 + tid];
        const float w1 = Wp1[1 * 256 + tid];
        const float w2 = Wp1[2 * 256 + tid];
        const float w3 = Wp1[3 * 256 + tid];
        const float b  = bp1[tid];
        #pragma unroll 8
        for (int e = 0; e < 32; e++) {
            float v = b + sX[e*4+0]*w0 + sX[e*4+1]*w1 + sX[e*4+2]*w2 + sX[e*4+3]*w3;
            h1[tid * 33 + e] = fmaxf(v, 0.0f);   // k-major store
        }
    }
    __syncthreads();

    const int te = tid & 7;        // edge group (4 edges each)
    const int tn = tid >> 3;       // 0..31 column group (8 cols each)
    const int el = te * 4;
    const int n0 = tn * 8;

    // ---- layer 2: h2 = relu(h1 @ Wp2 + bp2), thread tile 4e x 8n ----
    unsigned long long acc[4][4];
    {
        const float4 blo = *(const float4*)&bp2[n0];
        const float4 bhi = *(const float4*)&bp2[n0 + 4];
        const unsigned long long p0 = pack2(blo.x, blo.y), p1 = pack2(blo.z, blo.w);
        const unsigned long long p2 = pack2(bhi.x, bhi.y), p3 = pack2(bhi.z, bhi.w);
        #pragma unroll
        for (int i = 0; i < 4; i++) { acc[i][0]=p0; acc[i][1]=p1; acc[i][2]=p2; acc[i][3]=p3; }

        for (int kc = 0; kc < 8; kc++) {
            __syncthreads();
            const float4* src = (const float4*)(Wp2 + kc * 32 * 256);
            float4* dst = (float4*)wc;
            #pragma unroll
            for (int i = 0; i < 8; i++) dst[tid + i * 256] = src[tid + i * 256];
            __syncthreads();
            #pragma unroll
            for (int k = 0; k < 32; k++) {
                const float* hrow = &h1[(kc * 32 + k) * 33 + el];
                const unsigned long long a0 = dup2(hrow[0]);
                const unsigned long long a1 = dup2(hrow[1]);
                const unsigned long long a2 = dup2(hrow[2]);
                const unsigned long long a3 = dup2(hrow[3]);
                const ulonglong2 q0 = *(const ulonglong2*)&wc[k * 256 + n0];
                const ulonglong2 q1 = *(const ulonglong2*)&wc[k * 256 + n0 + 4];
                fma2(acc[0][0], a0, q0.x); fma2(acc[0][1], a0, q0.y);
                fma2(acc[0][2], a0, q1.x); fma2(acc[0][3], a0, q1.y);
                fma2(acc[1][0], a1, q0.x); fma2(acc[1][1], a1, q0.y);
                fma2(acc[1][2], a1, q1.x); fma2(acc[1][3], a1, q1.y);
                fma2(acc[2][0], a2, q0.x); fma2(acc[2][1], a2, q0.y);
                fma2(acc[2][2], a2, q1.x); fma2(acc[2][3], a2, q1.y);
                fma2(acc[3][0], a3, q0.x); fma2(acc[3][1], a3, q0.y);
                fma2(acc[3][2], a3, q1.x); fma2(acc[3][3], a3, q1.y);
            }
        }
        #pragma unroll
        for (int i = 0; i < 4; i++) {
            #pragma unroll
            for (int j = 0; j < 4; j++) {
                float lo, hi; unpack2(acc[i][j], lo, hi);
                h2[(n0 + 2*j    ) * 33 + el + i] = fmaxf(lo, 0.0f);
                h2[(n0 + 2*j + 1) * 33 + el + i] = fmaxf(hi, 0.0f);
            }
        }
    }

    // ---- layer 3: h3 = h2 @ Wp3 + bp3, thread tile 4e x 2n ----
    {
        const int c0 = tn * 2;     // 0..62
        unsigned long long acc3[4];
        const unsigned long long binit = pack2(bp3[c0], bp3[c0 + 1]);
        #pragma unroll
        for (int i = 0; i < 4; i++) acc3[i] = binit;

        for (int kc = 0; kc < 8; kc++) {
            __syncthreads();
            const float4* src = (const float4*)(Wp3 + kc * 32 * 64);
            float4* dst = (float4*)wc;
            dst[tid]       = src[tid];
            dst[tid + 256] = src[tid + 256];
            __syncthreads();
            #pragma unroll
            for (int k = 0; k < 32; k++) {
                const float* hrow = &h2[(kc * 32 + k) * 33 + el];
                const unsigned long long b = *(const unsigned long long*)&wc[k * 64 + c0];
                fma2(acc3[0], dup2(hrow[0]), b);
                fma2(acc3[1], dup2(hrow[1]), b);
                fma2(acc3[2], dup2(hrow[2]), b);
                fma2(acc3[3], dup2(hrow[3]), b);
            }
        }
        #pragma unroll
        for (int i = 0; i < 4; i++) {
            float lo, hi; unpack2(acc3[i], lo, hi);
            h3[(el + i) * 66 + c0]     = lo;
            h3[(el + i) * 66 + c0 + 1] = hi;
        }
    }

    // ---- analytic barrier per edge ----
    if (tid < 32) {
        const float px = sX[tid * 4 + 0];
        const float py = sX[tid * 4 + 1];
        const float d  = sqrtf(px * px + py * py);
        const float s  = -1.0f / (d * (d - (float)(1.2 * 0.15)));
        h3[tid * 66 + 64] = px * s;
        h3[tid * 66 + 65] = py * s;
    }
    __syncthreads();

    // ---- segmented reduce (ids sorted) -> global atomics ----
    if (tid < 66) {
        int cur = sseg[0];
        float run = 0.0f;
        #pragma unroll 1
        for (int e = 0; e < 32; e++) {
            const int s = sseg[e];
            if (s != cur) { atomicAdd(&g_agg[cur * 66 + tid], run); run = 0.0f; cur = s; }
            run += h3[e * 66 + tid];
        }
        atomicAdd(&g_agg[cur * 66 + tid], run);
    }
}

__global__ void zero_kernel() {
    const int i = blockIdx.x * blockDim.x + threadIdx.x;
    if (i < N_AG * AGG_STRIDE) g_agg[i] = 0.0f;
}

// agent kernel smem: g1[64][33]=2112, h2[256][33]=8448, r2[256][33]=8448,
//                    wc[32][256]=8192, w3[512]
#define AGENT_SMEM_FLOATS (2112 + 8448 + 8448 + 8192 + 512)
#define AGENT_SMEM_BYTES  (AGENT_SMEM_FLOATS * 4)

__global__ void __launch_bounds__(NTHREADS, 2) agent_kernel(
    const float* __restrict__ Wr1, const float* __restrict__ br1,
    const float* __restrict__ Wr2, const float* __restrict__ br2,
    const float* __restrict__ Wr3, const float* __restrict__ br3,
    float* __restrict__ out)
{
    extern __shared__ float sm[];
    float* g1 = sm;                 // 2112
    float* h2 = g1 + 2112;          // 8448
    float* r2 = h2 + 8448;          // 8448
    float* wc = r2 + 8448;          // 8192
    float* w3 = wc + 8192;          // 512

    const int tid = threadIdx.x;
    const int a0  = blockIdx.x * 32;

    // load agg tile k-major: g1[k][e]
    #pragma unroll
    for (int i = 0; i < 8; i++) {
        const int idx = tid + i * 256;      // 0..2047
        const int e = idx >> 6, k = idx & 63;
        g1[k * 33 + e] = g_agg[(a0 + e) * 66 + k];
    }
    w3[tid]       = Wr3[tid];
    w3[tid + 256] = Wr3[tid + 256];
    __syncthreads();

    const int te = tid & 7;
    const int tn = tid >> 3;
    const int el = te * 4;
    const int n0 = tn * 8;

    unsigned long long acc[4][4];

    // ---- r1 = relu(agg @ Wr1 + br1), K=64 ----
    {
        const float4 blo = *(const float4*)&br1[n0];
        const float4 bhi = *(const float4*)&br1[n0 + 4];
        const unsigned long long p0 = pack2(blo.x, blo.y), p1 = pack2(blo.z, blo.w);
        const unsigned long long p2 = pack2(bhi.x, bhi.y), p3 = pack2(bhi.z, bhi.w);
        #pragma unroll
        for (int i = 0; i < 4; i++) { acc[i][0]=p0; acc[i][1]=p1; acc[i][2]=p2; acc[i][3]=p3; }

        for (int kc = 0; kc < 2; kc++) {
            __syncthreads();
            const float4* src = (const float4*)(Wr1 + kc * 32 * 256);
            float4* dst = (float4*)wc;
            #pragma unroll
            for (int i = 0; i < 8; i++) dst[tid + i * 256] = src[tid + i * 256];
            __syncthreads();
            #pragma unroll
            for (int k = 0; k < 32; k++) {
                const float* hrow = &g1[(kc * 32 + k) * 33 + el];
                const unsigned long long a0d = dup2(hrow[0]);
                const unsigned long long a1d = dup2(hrow[1]);
                const unsigned long long a2d = dup2(hrow[2]);
                const unsigned long long a3d = dup2(hrow[3]);
                const ulonglong2 q0 = *(const ulonglong2*)&wc[k * 256 + n0];
                const ulonglong2 q1 = *(const ulonglong2*)&wc[k * 256 + n0 + 4];
                fma2(acc[0][0], a0d, q0.x); fma2(acc[0][1], a0d, q0.y);
                fma2(acc[0][2], a0d, q1.x); fma2(acc[0][3], a0d, q1.y);
                fma2(acc[1][0], a1d, q0.x); fma2(acc[1][1], a1d, q0.y);
                fma2(acc[1][2], a1d, q1.x); fma2(acc[1][3], a1d, q1.y);
                fma2(acc[2][0], a2d, q0.x); fma2(acc[2][1], a2d, q0.y);
                fma2(acc[2][2], a2d, q1.x); fma2(acc[2][3], a2d, q1.y);
                fma2(acc[3][0], a3d, q0.x); fma2(acc[3][1], a3d, q0.y);
                fma2(acc[3][2], a3d, q1.x); fma2(acc[3][3], a3d, q1.y);
            }
        }
        #pragma unroll
        for (int i = 0; i < 4; i++)
            #pragma unroll
            for (int j = 0; j < 4; j++) {
                float lo, hi; unpack2(acc[i][j], lo, hi);
                h2[(n0 + 2*j    ) * 33 + el + i] = fmaxf(lo, 0.0f);
                h2[(n0 + 2*j + 1) * 33 + el + i] = fmaxf(hi, 0.0f);
            }
    }

    // ---- r2 = relu(r1 @ Wr2 + br2), K=256 ----
    {
        const float4 blo = *(const float4*)&br2[n0];
        const float4 bhi = *(const float4*)&br2[n0 + 4];
        const unsigned long long p0 = pack2(blo.x, blo.y), p1 = pack2(blo.z, blo.w);
        const unsigned long long p2 = pack2(bhi.x, bhi.y), p3 = pack2(bhi.z, bhi.w);
        #pragma unroll
        for (int i = 0; i < 4; i++) { acc[i][0]=p0; acc[i][1]=p1; acc[i][2]=p2; acc[i][3]=p3; }

        for (int kc = 0; kc < 8; kc++) {
            __syncthreads();
            const float4* src = (const float4*)(Wr2 + kc * 32 * 256);
            float4* dst = (float4*)wc;
            #pragma unroll
            for (int i = 0; i < 8; i++) dst[tid + i * 256] = src[tid + i * 256];
            __syncthreads();
            #pragma unroll
            for (int k = 0; k < 32; k++) {
                const float* hrow = &h2[(kc * 32 + k) * 33 + el];
                const unsigned long long a0d = dup2(hrow[0]);
                const unsigned long long a1d = dup2(hrow[1]);
                const unsigned long long a2d = dup2(hrow[2]);
                const unsigned long long a3d = dup2(hrow[3]);
                const ulonglong2 q0 = *(const ulonglong2*)&wc[k * 256 + n0];
                const ulonglong2 q1 = *(const ulonglong2*)&wc[k * 256 + n0 + 4];
                fma2(acc[0][0], a0d, q0.x); fma2(acc[0][1], a0d, q0.y);
                fma2(acc[0][2], a0d, q1.x); fma2(acc[0][3], a0d, q1.y);
                fma2(acc[1][0], a1d, q0.x); fma2(acc[1][1], a1d, q0.y);
                fma2(acc[1][2], a1d, q1.x); fma2(acc[1][3], a1d, q1.y);
                fma2(acc[2][0], a2d, q0.x); fma2(acc[2][1], a2d, q0.y);
                fma2(acc[2][2], a2d, q1.x); fma2(acc[2][3], a2d, q1.y);
                fma2(acc[3][0], a3d, q0.x); fma2(acc[3][1], a3d, q0.y);
                fma2(acc[3][2], a3d, q1.x); fma2(acc[3][3], a3d, q1.y);
            }
        }
        #pragma unroll
        for (int i = 0; i < 4; i++)
            #pragma unroll
            for (int j = 0; j < 4; j++) {
                float lo, hi; unpack2(acc[i][j], lo, hi);
                r2[(n0 + 2*j    ) * 33 + el + i] = fmaxf(lo, 0.0f);
                r2[(n0 + 2*j + 1) * 33 + el + i] = fmaxf(hi, 0.0f);
            }
    }
    __syncthreads();

    // ---- final: out = r2 @ Wr3 + br3 + barrier ----
    if (tid < 64) {
        const int e = tid >> 1, c = tid & 1;
        float sum = br3[c];
        #pragma unroll 8
        for (int k = 0; k < 256; k++)
            sum += r2[k * 33 + e] * w3[k * 2 + c];
        out[(a0 + e) * 2 + c] = sum + g_agg[(a0 + e) * 66 + 64 + c];
    }
}

extern "C" void kernel_launch(void* const* d_in, const int* in_sizes, int n_in,
                              void* d_out, int out_size) {
    const float* ef  = (const float*)d_in[0];
    const int*   seg = (const int*)  d_in[1];
    const float* Wp1 = (const float*)d_in[2];
    const float* bp1 = (const float*)d_in[3];
    const float* Wp2 = (const float*)d_in[4];
    const float* bp2 = (const float*)d_in[5];
    const float* Wp3 = (const float*)d_in[6];
    const float* bp3 = (const float*)d_in[7];
    const float* Wr1 = (const float*)d_in[8];
    const float* br1 = (const float*)d_in[9];
    const float* Wr2 = (const float*)d_in[10];
    const float* br2 = (const float*)d_in[11];
    const float* Wr3 = (const float*)d_in[12];
    const float* br3 = (const float*)d_in[13];
    float* out = (float*)d_out;

    cudaFuncSetAttribute(edge_kernel,  cudaFuncAttributeMaxDynamicSharedMemorySize, EDGE_SMEM_BYTES);
    cudaFuncSetAttribute(agent_kernel, cudaFuncAttributeMaxDynamicSharedMemorySize, AGENT_SMEM_BYTES);

    zero_kernel<<<(N_AG * AGG_STRIDE + 255) / 256, 256>>>();
    edge_kernel<<<E_TOTAL / TILE_E, NTHREADS, EDGE_SMEM_BYTES>>>(
        ef, seg, Wp1, bp1, Wp2, bp2, Wp3, bp3);
    agent_kernel<<<N_AG / 32, NTHREADS, AGENT_SMEM_BYTES>>>(
        Wr1, br1, Wr2, br2, Wr3, br3, out);
}

// round 4
// speedup vs baseline: 3.0513x; 3.0425x over previous
#include <cuda_runtime.h>
#include <cuda_bf16.h>
#include <stdint.h>

#define E_TOTAL   524288
#define N_AG      16384
#define AGG_STRIDE 66   // 64 MLP feats + 2 barrier components

// tcgen05 is an arch-specific ('a') feature: only emit it in the sm_103a/sm_100a pass.
#if defined(__CUDA_ARCH_FEAT_SM103_ALL) || defined(__CUDA_ARCH_FEAT_SM100_ALL) || \
    (defined(__CUDA_ARCH_SPECIFIC__) && (__CUDA_ARCH_SPECIFIC__ >= 1000))
#define HAS_TCGEN05 1
#else
#define HAS_TCGEN05 0
#endif

// ---------------- device scratch (alloc-free rule) ----------------
__device__ float g_agg[N_AG * AGG_STRIDE];
__device__ __nv_bfloat16 g_Wp2T_hi[256 * 256];
__device__ __nv_bfloat16 g_Wp2T_lo[256 * 256];
__device__ __nv_bfloat16 g_Wp3T_hi[64 * 256];
__device__ __nv_bfloat16 g_Wp3T_lo[64 * 256];

// ---------------- common helpers ----------------
__device__ __forceinline__ uint32_t smem_u32(const void* p) {
    uint32_t a;
    asm("{ .reg .u64 t; cvta.to.shared.u64 t, %1; cvt.u32.u64 %0, t; }" : "=r"(a) : "l"(p));
    return a;
}
__device__ __forceinline__ uint32_t swz128(uint32_t off) { return off ^ ((off >> 3) & 0x70); }

__device__ __forceinline__ void split2(float v0, float v1, uint32_t& hi, uint32_t& lo) {
    __nv_bfloat16 h0 = __float2bfloat16(v0);
    __nv_bfloat16 h1 = __float2bfloat16(v1);
    float r0 = v0 - __bfloat162float(h0);
    float r1 = v1 - __bfloat162float(h1);
    __nv_bfloat16 l0 = __float2bfloat16(r0);
    __nv_bfloat16 l1 = __float2bfloat16(r1);
    hi = (uint32_t)__bfloat16_as_ushort(h0) | ((uint32_t)__bfloat16_as_ushort(h1) << 16);
    lo = (uint32_t)__bfloat16_as_ushort(l0) | ((uint32_t)__bfloat16_as_ushort(l1) << 16);
}

#if HAS_TCGEN05
// SW128 K-major smem descriptor (LBO=1, SBO=64, version=1)
__device__ __forceinline__ uint64_t mk_desc(uint32_t addr) {
    const uint64_t base = (uint64_t(2) << 61) | (uint64_t(1) << 46) | (uint64_t(64) << 32) | (uint64_t(1) << 16);
    return base | ((uint64_t)(addr >> 4) & 0x3FFF);
}
__device__ __forceinline__ void mma_f16_ss(uint32_t d, uint64_t a, uint64_t b, uint32_t idesc, uint32_t en) {
    asm volatile(
        "{\n\t.reg .pred p;\n\tsetp.ne.u32 p, %5, 0;\n\t"
        "tcgen05.mma.cta_group::1.kind::f16 [%0], %1, %2, %3, {%4,%4,%4,%4}, p;\n\t}"
        :: "r"(d), "l"(a), "l"(b), "r"(idesc), "r"(0u), "r"(en) : "memory");
}
#define TC_ALLOC(sa, n)   asm volatile("tcgen05.alloc.cta_group::1.sync.aligned.shared::cta.b32 [%0], %1;" :: "r"(sa), "r"(n) : "memory")
#define TC_RELINQ()       asm volatile("tcgen05.relinquish_alloc_permit.cta_group::1.sync.aligned;")
#define TC_DEALLOC(t, n)  asm volatile("tcgen05.dealloc.cta_group::1.sync.aligned.b32 %0, %1;" :: "r"(t), "r"(n))
#define TC_COMMIT(mb)     asm volatile("tcgen05.commit.cta_group::1.mbarrier::arrive::one.shared::cluster.b64 [%0];" :: "r"(mb) : "memory")
#define TC_FENCE_AFTER()  asm volatile("tcgen05.fence::after_thread_sync;" ::: "memory")
#define TC_WAIT_LD()      asm volatile("tcgen05.wait::ld.sync.aligned;" ::: "memory")
#define FENCE_ASYNC()     asm volatile("fence.proxy.async.shared::cta;" ::: "memory")
#define MBAR_INIT(mb, c)  asm volatile("mbarrier.init.shared.b64 [%0], %1;" :: "r"(mb), "r"(c) : "memory")

#define MBAR_WAIT(mb, par) do { \
    uint32_t _m = (mb); uint32_t _p = (par); uint32_t _d; \
    asm volatile("{\n\t.reg .pred p;\n\t" \
        "mbarrier.try_wait.parity.acquire.cta.shared::cta.b64 p, [%1], %2;\n\t" \
        "selp.b32 %0, 1, 0, p;\n\t}" : "=r"(_d) : "r"(_m), "r"(_p) : "memory"); \
    if (!_d) { \
        asm volatile("{\n\t.reg .pred P1;\n\t" \
            "WL_%=:\n\t" \
            "mbarrier.try_wait.parity.acquire.cta.shared::cta.b64 P1, [%0], %1, 0x989680;\n\t" \
            "@P1 bra.uni WD_%=;\n\t" \
            "bra.uni WL_%=;\n\t" \
            "WD_%=:\n\t}" :: "r"(_m), "r"(_p) : "memory"); \
    } \
} while (0)

#define TC_LD_X32(r, ta) \
    asm volatile("tcgen05.ld.sync.aligned.32x32b.x32.b32 " \
        "{%0,%1,%2,%3,%4,%5,%6,%7,%8,%9,%10,%11,%12,%13,%14,%15," \
        "%16,%17,%18,%19,%20,%21,%22,%23,%24,%25,%26,%27,%28,%29,%30,%31}, [%32];" \
        : "=r"((r)[0]),"=r"((r)[1]),"=r"((r)[2]),"=r"((r)[3]),"=r"((r)[4]),"=r"((r)[5]),"=r"((r)[6]),"=r"((r)[7]), \
          "=r"((r)[8]),"=r"((r)[9]),"=r"((r)[10]),"=r"((r)[11]),"=r"((r)[12]),"=r"((r)[13]),"=r"((r)[14]),"=r"((r)[15]), \
          "=r"((r)[16]),"=r"((r)[17]),"=r"((r)[18]),"=r"((r)[19]),"=r"((r)[20]),"=r"((r)[21]),"=r"((r)[22]),"=r"((r)[23]), \
          "=r"((r)[24]),"=r"((r)[25]),"=r"((r)[26]),"=r"((r)[27]),"=r"((r)[28]),"=r"((r)[29]),"=r"((r)[30]),"=r"((r)[31]) \
        : "r"(ta))
#endif // HAS_TCGEN05

// idesc: dtype=F32(1<<4), atype=BF16(1<<7), btype=BF16(1<<10), N>>3 <<17, M>>4 <<24
#define IDESC_N128 0x8200490u
#define IDESC_N64  0x8100490u

// ---------------- smem layout (bytes), edge kernel ----------------
#define OFF_TMEM  0
#define OFF_MBAR0 16
#define OFF_MBAR1 24
#define OFF_SSEG  32      // 128 ints
#define OFF_BP2   544     // 256 f
#define OFF_BP3   1568    // 64 f
#define OFF_BP1   1824    // 256 f
#define OFF_WP1   2848    // 1024 f
#define OFF_A0    7168    // 32KB: hi 16K + lo 16K
#define OFF_A1    39936
#define OFF_B0    72704   // 64KB: hi 32K + lo 32K
#define OFF_B1    138240
#define EDGE_SMEM 203776

// ---------------- weight prep: transpose + bf16 split ----------------
__global__ void prep_kernel(const float* __restrict__ Wp2, const float* __restrict__ Wp3) {
    int i = blockIdx.x * blockDim.x + threadIdx.x;
    if (i < 256 * 256) {
        int n = i >> 8, k = i & 255;
        float w = Wp2[k * 256 + n];
        __nv_bfloat16 h = __float2bfloat16(w);
        float r = w - __bfloat162float(h);
        g_Wp2T_hi[n * 256 + k] = h;
        g_Wp2T_lo[n * 256 + k] = __float2bfloat16(r);
    }
    if (i < 64 * 256) {
        int n = i >> 8, k = i & 255;
        float w = Wp3[k * 64 + n];
        __nv_bfloat16 h = __float2bfloat16(w);
        float r = w - __bfloat162float(h);
        g_Wp3T_hi[n * 256 + k] = h;
        g_Wp3T_lo[n * 256 + k] = __float2bfloat16(r);
    }
}

__global__ void zero_kernel() {
    const int i = blockIdx.x * blockDim.x + threadIdx.x;
    if (i < N_AG * AGG_STRIDE) g_agg[i] = 0.0f;
}

// ---------------- edge kernel: fused MLP on tcgen05 ----------------
__global__ void __launch_bounds__(128, 1) edge_kernel(
    const float* __restrict__ ef, const int* __restrict__ seg,
    const float* __restrict__ Wp1, const float* __restrict__ bp1,
    const float* __restrict__ bp2, const float* __restrict__ bp3,
    const float* __restrict__ Wp2g, const float* __restrict__ Wp3g)
{
    extern __shared__ char sm[];
    const uint32_t smb = smem_u32(sm);
    const int tid = threadIdx.x;
    const int wid = tid >> 5;
    const int e0 = blockIdx.x * 128;

    int*   sseg = (int*)(sm + OFF_SSEG);
    float* bp2s = (float*)(sm + OFF_BP2);
    float* bp3s = (float*)(sm + OFF_BP3);
    float* bp1s = (float*)(sm + OFF_BP1);
    float* wp1s = (float*)(sm + OFF_WP1);

#if HAS_TCGEN05
    if (wid == 0) { TC_ALLOC(smb + OFF_TMEM, 512); TC_RELINQ(); }
    if (tid == 0) { MBAR_INIT(smb + OFF_MBAR0, 1); MBAR_INIT(smb + OFF_MBAR1, 1); }
#endif

    const float4 x = ((const float4*)ef)[e0 + tid];
    sseg[tid] = seg[e0 + tid];
    wp1s[tid] = Wp1[tid];       wp1s[tid + 128] = Wp1[tid + 128];
    wp1s[tid + 256] = Wp1[tid + 256]; wp1s[tid + 384] = Wp1[tid + 384];
    wp1s[tid + 512] = Wp1[tid + 512]; wp1s[tid + 640] = Wp1[tid + 640];
    wp1s[tid + 768] = Wp1[tid + 768]; wp1s[tid + 896] = Wp1[tid + 896];
    bp1s[tid] = bp1[tid]; bp1s[tid + 128] = bp1[tid + 128];
    bp2s[tid] = bp2[tid]; bp2s[tid + 128] = bp2[tid + 128];
    if (tid < 64) bp3s[tid] = bp3[tid];
    __syncthreads();

    float* h3T = (float*)(sm + OFF_B0);   // [66][132] epilogue staging

#if HAS_TCGEN05
    uint32_t tmem;
    asm volatile("ld.shared.b32 %0, [%1];" : "=r"(tmem) : "r"(smb + OFF_TMEM));
    const uint32_t tD2 = tmem;        // 256 cols
    const uint32_t tD3 = tmem + 256;  // 64 cols
    int p0 = 0, p1 = 0;

    // ================= layer 2: K=256 in 4 chunks of 64 =================
    for (int kc = 0; kc < 4; kc++) {
        if (kc >= 2) {
            if ((kc & 1) == 0) { MBAR_WAIT(smb + OFF_MBAR0, p0); p0 ^= 1; }
            else               { MBAR_WAIT(smb + OFF_MBAR1, p1); p1 ^= 1; }
        }
        char* A = sm + ((kc & 1) ? OFF_A1 : OFF_A0);
        char* B = sm + ((kc & 1) ? OFF_B1 : OFF_B0);

        // ---- layer 1 on the fly: h1 cols [kc*64, kc*64+64), split & store ----
        #pragma unroll
        for (int g = 0; g < 8; g++) {
            uint32_t hi4[4], lo4[4];
            #pragma unroll
            for (int q = 0; q < 4; q++) {
                const int c = kc * 64 + g * 8 + q * 2;
                float v0 = fmaf(x.x, wp1s[c],       fmaf(x.y, wp1s[256 + c],
                           fmaf(x.z, wp1s[512 + c], fmaf(x.w, wp1s[768 + c], bp1s[c]))));
                float v1 = fmaf(x.x, wp1s[c + 1],       fmaf(x.y, wp1s[256 + c + 1],
                           fmaf(x.z, wp1s[512 + c + 1], fmaf(x.w, wp1s[768 + c + 1], bp1s[c + 1]))));
                v0 = fmaxf(v0, 0.0f); v1 = fmaxf(v1, 0.0f);
                split2(v0, v1, hi4[q], lo4[q]);
            }
            const uint32_t so = swz128(tid * 128 + g * 16);
            *(uint4*)(A + so)         = make_uint4(hi4[0], hi4[1], hi4[2], hi4[3]);
            *(uint4*)(A + 16384 + so) = make_uint4(lo4[0], lo4[1], lo4[2], lo4[3]);
        }

        // ---- stream Wp2T chunk [256 rows x 64 k] hi+lo ----
        #pragma unroll
        for (int it = 0; it < 16; it++) {
            const int idx = tid + it * 128;
            const int n = idx >> 3, sg = idx & 7;
            const uint4 vh = ((const uint4*)(g_Wp2T_hi + n * 256 + kc * 64))[sg];
            const uint4 vl = ((const uint4*)(g_Wp2T_lo + n * 256 + kc * 64))[sg];
            const uint32_t so = swz128(n * 128 + sg * 16);
            *(uint4*)(B + so)         = vh;
            *(uint4*)(B + 32768 + so) = vl;
        }
        FENCE_ASYNC();
        __syncthreads();

        if (tid == 0) {
            const uint64_t dAh = mk_desc(smb + (uint32_t)(A - sm));
            const uint64_t dAl = dAh + 1024;   // +16KB
            const uint64_t dBh = mk_desc(smb + (uint32_t)(B - sm));
            const uint64_t dBl = dBh + 2048;   // +32KB
            #pragma unroll
            for (int s = 0; s < 4; s++) {
                #pragma unroll
                for (int h = 0; h < 2; h++) {
                    const uint32_t d = tD2 + h * 128;
                    const uint64_t bo = (uint64_t)h * 1024 + s * 2;  // +16KB per N-half
                    mma_f16_ss(d, dAh + s * 2, dBh + bo, IDESC_N128, !(kc == 0 && s == 0));
                    mma_f16_ss(d, dAh + s * 2, dBl + bo, IDESC_N128, 1);
                    mma_f16_ss(d, dAl + s * 2, dBh + bo, IDESC_N128, 1);
                }
            }
            TC_COMMIT(smb + ((kc & 1) ? OFF_MBAR1 : OFF_MBAR0));
        }
        __syncthreads();
    }

    // all layer-2 MMAs done
    MBAR_WAIT(smb + OFF_MBAR0, p0); p0 ^= 1;
    MBAR_WAIT(smb + OFF_MBAR1, p1); p1 ^= 1;
    TC_FENCE_AFTER();

    // ================= layer 3: h2 slices -> D3 =================
    for (int i = 0; i < 4; i++) {
        if (i >= 2) {
            if ((i & 1) == 0) { MBAR_WAIT(smb + OFF_MBAR0, p0); p0 ^= 1; }
            else              { MBAR_WAIT(smb + OFF_MBAR1, p1); p1 ^= 1; }
        }
        uint32_t r0[32], r1[32];
        TC_LD_X32(r0, tD2 + i * 64);
        TC_LD_X32(r1, tD2 + i * 64 + 32);
        TC_WAIT_LD();

        char* A2 = sm + ((i & 1) ? OFF_A1 : OFF_A0);
        char* B3 = sm + OFF_B1 + (i & 1) * 16384;   // hi 8K + lo 8K

        #pragma unroll
        for (int g = 0; g < 4; g++) {
            uint32_t hi4[4], lo4[4];
            #pragma unroll
            for (int q = 0; q < 4; q++) {
                const int j = g * 8 + q * 2;
                const int c = i * 64 + j;
                float v0 = fmaxf(__uint_as_float(r0[j])     + bp2s[c],     0.0f);
                float v1 = fmaxf(__uint_as_float(r0[j + 1]) + bp2s[c + 1], 0.0f);
                split2(v0, v1, hi4[q], lo4[q]);
            }
            const uint32_t so = swz128(tid * 128 + g * 16);
            *(uint4*)(A2 + so)         = make_uint4(hi4[0], hi4[1], hi4[2], hi4[3]);
            *(uint4*)(A2 + 16384 + so) = make_uint4(lo4[0], lo4[1], lo4[2], lo4[3]);
        }
        #pragma unroll
        for (int g = 4; g < 8; g++) {
            uint32_t hi4[4], lo4[4];
            #pragma unroll
            for (int q = 0; q < 4; q++) {
                const int j = (g - 4) * 8 + q * 2;
                const int c = i * 64 + 32 + j;
                float v0 = fmaxf(__uint_as_float(r1[j])     + bp2s[c],     0.0f);
                float v1 = fmaxf(__uint_as_float(r1[j + 1]) + bp2s[c + 1], 0.0f);
                split2(v0, v1, hi4[q], lo4[q]);
            }
            const uint32_t so = swz128(tid * 128 + g * 16);
            *(uint4*)(A2 + so)         = make_uint4(hi4[0], hi4[1], hi4[2], hi4[3]);
            *(uint4*)(A2 + 16384 + so) = make_uint4(lo4[0], lo4[1], lo4[2], lo4[3]);
        }

        // Wp3T chunk [64 rows x 64 k] hi+lo
        #pragma unroll
        for (int it = 0; it < 4; it++) {
            const int idx = tid + it * 128;
            const int n = idx >> 3, sg = idx & 7;
            const uint4 vh = ((const uint4*)(g_Wp3T_hi + n * 256 + i * 64))[sg];
            const uint4 vl = ((const uint4*)(g_Wp3T_lo + n * 256 + i * 64))[sg];
            const uint32_t so = swz128(n * 128 + sg * 16);
            *(uint4*)(B3 + so)        = vh;
            *(uint4*)(B3 + 8192 + so) = vl;
        }
        FENCE_ASYNC();
        __syncthreads();

        if (tid == 0) {
            const uint64_t dAh = mk_desc(smb + (uint32_t)(A2 - sm));
            const uint64_t dAl = dAh + 1024;  // +16KB
            const uint64_t dBh = mk_desc(smb + (uint32_t)(B3 - sm));
            const uint64_t dBl = dBh + 512;   // +8KB
            #pragma unroll
            for (int s = 0; s < 4; s++) {
                mma_f16_ss(tD3, dAh + s * 2, dBh + s * 2, IDESC_N64, !(i == 0 && s == 0));
                mma_f16_ss(tD3, dAh + s * 2, dBl + s * 2, IDESC_N64, 1);
                mma_f16_ss(tD3, dAl + s * 2, dBh + s * 2, IDESC_N64, 1);
            }
            TC_COMMIT(smb + ((i & 1) ? OFF_MBAR1 : OFF_MBAR0));
        }
        __syncthreads();
    }

    MBAR_WAIT(smb + OFF_MBAR0, p0); p0 ^= 1;
    MBAR_WAIT(smb + OFF_MBAR1, p1); p1 ^= 1;
    TC_FENCE_AFTER();

    // h3 rows into column-major staging
    {
        uint32_t r0[32], r1[32];
        TC_LD_X32(r0, tD3);
        TC_LD_X32(r1, tD3 + 32);
        TC_WAIT_LD();

        #pragma unroll
        for (int c = 0; c < 32; c++)
            h3T[c * 132 + tid] = __uint_as_float(r0[c]) + bp3s[c];
        #pragma unroll
        for (int c = 0; c < 32; c++)
            h3T[(c + 32) * 132 + tid] = __uint_as_float(r1[c]) + bp3s[c + 32];
    }
#else
    // ---------- correct scalar fallback (compiled only for non-'a' targets) ----------
    {
        float* hbuf = (float*)(sm + OFF_A0);   // [256][128] k-major
        for (int k = 0; k < 256; k++) {
            float v = fmaf(x.x, wp1s[k],       fmaf(x.y, wp1s[256 + k],
                      fmaf(x.z, wp1s[512 + k], fmaf(x.w, wp1s[768 + k], bp1s[k]))));
            hbuf[k * 128 + tid] = fmaxf(v, 0.0f);
        }
        float h3a[64];
        for (int n = 0; n < 64; n++) h3a[n] = bp3s[n];
        for (int kc = 0; kc < 4; kc++) {
            float h2c[64];
            for (int j = 0; j < 64; j++) {
                const int c = kc * 64 + j;
                float s = bp2s[c];
                for (int k = 0; k < 256; k++)
                    s = fmaf(hbuf[k * 128 + tid], Wp2g[k * 256 + c], s);
                h2c[j] = fmaxf(s, 0.0f);
            }
            for (int j = 0; j < 64; j++) {
                const int r = kc * 64 + j;
                for (int n = 0; n < 64; n++)
                    h3a[n] = fmaf(h2c[j], Wp3g[r * 64 + n], h3a[n]);
            }
        }
        __syncthreads();   // hbuf region aliases h3T region? (A0 vs B0: distinct) — order writes anyway
        for (int c = 0; c < 64; c++)
            h3T[c * 132 + tid] = h3a[c];
    }
#endif

    // ================= epilogue: barrier term + segmented reduce =================
    {
        const float px = x.x, py = x.y;
        const float d = sqrtf(px * px + py * py);
        const float s = -1.0f / (d * (d - 0.18f));
        h3T[64 * 132 + tid] = px * s;
        h3T[65 * 132 + tid] = py * s;
        __syncthreads();

        if (tid < 66) {
            const float* col = h3T + tid * 132;
            int cur = sseg[0];
            float run = 0.0f;
            #pragma unroll 4
            for (int e = 0; e < 128; e++) {
                const int sg = sseg[e];
                if (sg != cur) { atomicAdd(&g_agg[cur * 66 + tid], run); run = 0.0f; cur = sg; }
                run += col[e];
            }
            atomicAdd(&g_agg[cur * 66 + tid], run);
        }
    }
    __syncthreads();
#if HAS_TCGEN05
    if (wid == 0) TC_DEALLOC(tmem, 512);
#endif
}

// ---------------- agent kernel (fp32x2 path, arch-portable) ----------------
__device__ __forceinline__ unsigned long long dup2(float a) {
    unsigned long long r;
    asm("mov.b64 %0, {%1, %1};" : "=l"(r) : "f"(a));
    return r;
}
__device__ __forceinline__ unsigned long long pack2(float lo, float hi) {
    unsigned long long r;
    asm("mov.b64 %0, {%1, %2};" : "=l"(r) : "f"(lo), "f"(hi));
    return r;
}
__device__ __forceinline__ void unpack2(unsigned long long v, float& lo, float& hi) {
    asm("mov.b64 {%0, %1}, %2;" : "=f"(lo), "=f"(hi) : "l"(v));
}
__device__ __forceinline__ void fma2(unsigned long long& acc, unsigned long long a, unsigned long long b) {
    asm("fma.rn.f32x2 %0, %1, %2, %0;" : "+l"(acc) : "l"(a), "l"(b));
}

#define AGENT_SMEM_FLOATS (2112 + 8448 + 8448 + 8192 + 512)
#define AGENT_SMEM_BYTES  (AGENT_SMEM_FLOATS * 4)

__global__ void __launch_bounds__(256, 2) agent_kernel(
    const float* __restrict__ Wr1, const float* __restrict__ br1,
    const float* __restrict__ Wr2, const float* __restrict__ br2,
    const float* __restrict__ Wr3, const float* __restrict__ br3,
    float* __restrict__ out)
{
    extern __shared__ float smf[];
    float* g1 = smf;
    float* h2 = g1 + 2112;
    float* r2 = h2 + 8448;
    float* wc = r2 + 8448;
    float* w3 = wc + 8192;

    const int tid = threadIdx.x;
    const int a0 = blockIdx.x * 32;

    #pragma unroll
    for (int i = 0; i < 8; i++) {
        const int idx = tid + i * 256;
        const int e = idx >> 6, k = idx & 63;
        g1[k * 33 + e] = g_agg[(a0 + e) * 66 + k];
    }
    w3[tid] = Wr3[tid];
    w3[tid + 256] = Wr3[tid + 256];
    __syncthreads();

    const int te = tid & 7;
    const int tn = tid >> 3;
    const int el = te * 4;
    const int n0 = tn * 8;

    unsigned long long acc[4][4];

    {   // r1 = relu(agg @ Wr1 + br1), K=64
        const float4 blo = *(const float4*)&br1[n0];
        const float4 bhi = *(const float4*)&br1[n0 + 4];
        const unsigned long long q0 = pack2(blo.x, blo.y), q1 = pack2(blo.z, blo.w);
        const unsigned long long q2 = pack2(bhi.x, bhi.y), q3 = pack2(bhi.z, bhi.w);
        #pragma unroll
        for (int i = 0; i < 4; i++) { acc[i][0]=q0; acc[i][1]=q1; acc[i][2]=q2; acc[i][3]=q3; }

        for (int kc = 0; kc < 2; kc++) {
            __syncthreads();
            const float4* src = (const float4*)(Wr1 + kc * 32 * 256);
            float4* dst = (float4*)wc;
            #pragma unroll
            for (int i = 0; i < 8; i++) dst[tid + i * 256] = src[tid + i * 256];
            __syncthreads();
            #pragma unroll
            for (int k = 0; k < 32; k++) {
                const float* hrow = &g1[(kc * 32 + k) * 33 + el];
                const unsigned long long a0d = dup2(hrow[0]);
                const unsigned long long a1d = dup2(hrow[1]);
                const unsigned long long a2d = dup2(hrow[2]);
                const unsigned long long a3d = dup2(hrow[3]);
                const ulonglong2 u0 = *(const ulonglong2*)&wc[k * 256 + n0];
                const ulonglong2 u1 = *(const ulonglong2*)&wc[k * 256 + n0 + 4];
                fma2(acc[0][0], a0d, u0.x); fma2(acc[0][1], a0d, u0.y);
                fma2(acc[0][2], a0d, u1.x); fma2(acc[0][3], a0d, u1.y);
                fma2(acc[1][0], a1d, u0.x); fma2(acc[1][1], a1d, u0.y);
                fma2(acc[1][2], a1d, u1.x); fma2(acc[1][3], a1d, u1.y);
                fma2(acc[2][0], a2d, u0.x); fma2(acc[2][1], a2d, u0.y);
                fma2(acc[2][2], a2d, u1.x); fma2(acc[2][3], a2d, u1.y);
                fma2(acc[3][0], a3d, u0.x); fma2(acc[3][1], a3d, u0.y);
                fma2(acc[3][2], a3d, u1.x); fma2(acc[3][3], a3d, u1.y);
            }
        }
        #pragma unroll
        for (int i = 0; i < 4; i++)
            #pragma unroll
            for (int j = 0; j < 4; j++) {
                float lo, hi; unpack2(acc[i][j], lo, hi);
                h2[(n0 + 2*j    ) * 33 + el + i] = fmaxf(lo, 0.0f);
                h2[(n0 + 2*j + 1) * 33 + el + i] = fmaxf(hi, 0.0f);
            }
    }

    {   // r2 = relu(r1 @ Wr2 + br2), K=256
        const float4 blo = *(const float4*)&br2[n0];
        const float4 bhi = *(const float4*)&br2[n0 + 4];
        const unsigned long long q0 = pack2(blo.x, blo.y), q1 = pack2(blo.z, blo.w);
        const unsigned long long q2 = pack2(bhi.x, bhi.y), q3 = pack2(bhi.z, bhi.w);
        #pragma unroll
        for (int i = 0; i < 4; i++) { acc[i][0]=q0; acc[i][1]=q1; acc[i][2]=q2; acc[i][3]=q3; }

        for (int kc = 0; kc < 8; kc++) {
            __syncthreads();
            const float4* src = (const float4*)(Wr2 + kc * 32 * 256);
            float4* dst = (float4*)wc;
            #pragma unroll
            for (int i = 0; i < 8; i++) dst[tid + i * 256] = src[tid + i * 256];
            __syncthreads();
            #pragma unroll
            for (int k = 0; k < 32; k++) {
                const float* hrow = &h2[(kc * 32 + k) * 33 + el];
                const unsigned long long a0d = dup2(hrow[0]);
                const unsigned long long a1d = dup2(hrow[1]);
                const unsigned long long a2d = dup2(hrow[2]);
                const unsigned long long a3d = dup2(hrow[3]);
                const ulonglong2 u0 = *(const ulonglong2*)&wc[k * 256 + n0];
                const ulonglong2 u1 = *(const ulonglong2*)&wc[k * 256 + n0 + 4];
                fma2(acc[0][0], a0d, u0.x); fma2(acc[0][1], a0d, u0.y);
                fma2(acc[0][2], a0d, u1.x); fma2(acc[0][3], a0d, u1.y);
                fma2(acc[1][0], a1d, u0.x); fma2(acc[1][1], a1d, u0.y);
                fma2(acc[1][2], a1d, u1.x); fma2(acc[1][3], a1d, u1.y);
                fma2(acc[2][0], a2d, u0.x); fma2(acc[2][1], a2d, u0.y);
                fma2(acc[2][2], a2d, u1.x); fma2(acc[2][3], a2d, u1.y);
                fma2(acc[3][0], a3d, u0.x); fma2(acc[3][1], a3d, u0.y);
                fma2(acc[3][2], a3d, u1.x); fma2(acc[3][3], a3d, u1.y);
            }
        }
        #pragma unroll
        for (int i = 0; i < 4; i++)
            #pragma unroll
            for (int j = 0; j < 4; j++) {
                float lo, hi; unpack2(acc[i][j], lo, hi);
                r2[(n0 + 2*j    ) * 33 + el + i] = fmaxf(lo, 0.0f);
                r2[(n0 + 2*j + 1) * 33 + el + i] = fmaxf(hi, 0.0f);
            }
    }
    __syncthreads();

    if (tid < 64) {
        const int e = tid >> 1, c = tid & 1;
        float sum = br3[c];
        #pragma unroll 8
        for (int k = 0; k < 256; k++)
            sum += r2[k * 33 + e] * w3[k * 2 + c];
        out[(a0 + e) * 2 + c] = sum + g_agg[(a0 + e) * 66 + 64 + c];
    }
}

// ---------------- launch ----------------
extern "C" void kernel_launch(void* const* d_in, const int* in_sizes, int n_in,
                              void* d_out, int out_size) {
    const float* ef  = (const float*)d_in[0];
    const int*   seg = (const int*)  d_in[1];
    const float* Wp1 = (const float*)d_in[2];
    const float* bp1 = (const float*)d_in[3];
    const float* Wp2 = (const float*)d_in[4];
    const float* bp2 = (const float*)d_in[5];
    const float* Wp3 = (const float*)d_in[6];
    const float* bp3 = (const float*)d_in[7];
    const float* Wr1 = (const float*)d_in[8];
    const float* br1 = (const float*)d_in[9];
    const float* Wr2 = (const float*)d_in[10];
    const float* br2 = (const float*)d_in[11];
    const float* Wr3 = (const float*)d_in[12];
    const float* br3 = (const float*)d_in[13];
    float* out = (float*)d_out;

    cudaFuncSetAttribute(edge_kernel,  cudaFuncAttributeMaxDynamicSharedMemorySize, EDGE_SMEM);
    cudaFuncSetAttribute(agent_kernel, cudaFuncAttributeMaxDynamicSharedMemorySize, AGENT_SMEM_BYTES);

    prep_kernel<<<256, 256>>>(Wp2, Wp3);
    zero_kernel<<<(N_AG * AGG_STRIDE + 255) / 256, 256>>>();
    edge_kernel<<<E_TOTAL / 128, 128, EDGE_SMEM>>>(ef, seg, Wp1, bp1, bp2, bp3, Wp2, Wp3);
    agent_kernel<<<N_AG / 32, 256, AGENT_SMEM_BYTES>>>(Wr1, br1, Wr2, br2, Wr3, br3, out);
}

// round 5
// speedup vs baseline: 4.2005x; 1.3766x over previous
#include <cuda_runtime.h>
#include <cuda_bf16.h>
#include <stdint.h>

#define E_TOTAL   524288
#define N_AG      16384
#define AGG_STRIDE 66   // 64 MLP feats + 2 barrier components

// tcgen05 is an arch-specific ('a') feature: only emit it in the sm_103a/sm_100a pass.
#if defined(__CUDA_ARCH_FEAT_SM103_ALL) || defined(__CUDA_ARCH_FEAT_SM100_ALL) || \
    (defined(__CUDA_ARCH_SPECIFIC__) && (__CUDA_ARCH_SPECIFIC__ >= 1000))
#define HAS_TCGEN05 1
#else
#define HAS_TCGEN05 0
#endif

// ---------------- device scratch (alloc-free rule) ----------------
__device__ float g_agg[N_AG * AGG_STRIDE];
__device__ __nv_bfloat16 g_Wp2T_hi[256 * 256];
__device__ __nv_bfloat16 g_Wp2T_lo[256 * 256];
__device__ __nv_bfloat16 g_Wp3T_hi[64 * 256];
__device__ __nv_bfloat16 g_Wp3T_lo[64 * 256];

// ---------------- common helpers ----------------
__device__ __forceinline__ uint32_t smem_u32(const void* p) {
    uint32_t a;
    asm("{ .reg .u64 t; cvta.to.shared.u64 t, %1; cvt.u32.u64 %0, t; }" : "=r"(a) : "l"(p));
    return a;
}
__device__ __forceinline__ uint32_t swz128(uint32_t off) { return off ^ ((off >> 3) & 0x70); }

// Fast truncation split: hi = top-16 bits (exact bf16), lo = v - hi (exact fp32),
// truncated to bf16. PRMT packs two high halves in one instruction.
__device__ __forceinline__ void split2(float v0, float v1, uint32_t& hi, uint32_t& lo) {
    const uint32_t u0 = __float_as_uint(v0), u1 = __float_as_uint(v1);
    hi = __byte_perm(u0, u1, 0x7632);
    const float l0 = v0 - __uint_as_float(u0 & 0xFFFF0000u);
    const float l1 = v1 - __uint_as_float(u1 & 0xFFFF0000u);
    lo = __byte_perm(__float_as_uint(l0), __float_as_uint(l1), 0x7632);
}

#if HAS_TCGEN05
// SW128 K-major smem descriptor (LBO=1, SBO=64, version=1)
__device__ __forceinline__ uint64_t mk_desc(uint32_t addr) {
    const uint64_t base = (uint64_t(2) << 61) | (uint64_t(1) << 46) | (uint64_t(64) << 32) | (uint64_t(1) << 16);
    return base | ((uint64_t)(addr >> 4) & 0x3FFF);
}
__device__ __forceinline__ void mma_f16_ss(uint32_t d, uint64_t a, uint64_t b, uint32_t idesc, uint32_t en) {
    asm volatile(
        "{\n\t.reg .pred p;\n\tsetp.ne.u32 p, %5, 0;\n\t"
        "tcgen05.mma.cta_group::1.kind::f16 [%0], %1, %2, %3, {%4,%4,%4,%4}, p;\n\t}"
        :: "r"(d), "l"(a), "l"(b), "r"(idesc), "r"(0u), "r"(en) : "memory");
}
#define TC_ALLOC(sa, n)   asm volatile("tcgen05.alloc.cta_group::1.sync.aligned.shared::cta.b32 [%0], %1;" :: "r"(sa), "r"(n) : "memory")
#define TC_RELINQ()       asm volatile("tcgen05.relinquish_alloc_permit.cta_group::1.sync.aligned;")
#define TC_DEALLOC(t, n)  asm volatile("tcgen05.dealloc.cta_group::1.sync.aligned.b32 %0, %1;" :: "r"(t), "r"(n))
#define TC_COMMIT(mb)     asm volatile("tcgen05.commit.cta_group::1.mbarrier::arrive::one.shared::cluster.b64 [%0];" :: "r"(mb) : "memory")
#define TC_FENCE_AFTER()  asm volatile("tcgen05.fence::after_thread_sync;" ::: "memory")
#define TC_WAIT_LD()      asm volatile("tcgen05.wait::ld.sync.aligned;" ::: "memory")
#define FENCE_ASYNC()     asm volatile("fence.proxy.async.shared::cta;" ::: "memory")
#define MBAR_INIT(mb, c)  asm volatile("mbarrier.init.shared.b64 [%0], %1;" :: "r"(mb), "r"(c) : "memory")

#define MBAR_WAIT(mb, par) do { \
    uint32_t _m = (mb); uint32_t _p = (par); uint32_t _d; \
    asm volatile("{\n\t.reg .pred p;\n\t" \
        "mbarrier.try_wait.parity.acquire.cta.shared::cta.b64 p, [%1], %2;\n\t" \
        "selp.b32 %0, 1, 0, p;\n\t}" : "=r"(_d) : "r"(_m), "r"(_p) : "memory"); \
    if (!_d) { \
        asm volatile("{\n\t.reg .pred P1;\n\t" \
            "WL_%=:\n\t" \
            "mbarrier.try_wait.parity.acquire.cta.shared::cta.b64 P1, [%0], %1, 0x989680;\n\t" \
            "@P1 bra.uni WD_%=;\n\t" \
            "bra.uni WL_%=;\n\t" \
            "WD_%=:\n\t}" :: "r"(_m), "r"(_p) : "memory"); \
    } \
} while (0)

#define TC_LD_X32(r, ta) \
    asm volatile("tcgen05.ld.sync.aligned.32x32b.x32.b32 " \
        "{%0,%1,%2,%3,%4,%5,%6,%7,%8,%9,%10,%11,%12,%13,%14,%15," \
        "%16,%17,%18,%19,%20,%21,%22,%23,%24,%25,%26,%27,%28,%29,%30,%31}, [%32];" \
        : "=r"((r)[0]),"=r"((r)[1]),"=r"((r)[2]),"=r"((r)[3]),"=r"((r)[4]),"=r"((r)[5]),"=r"((r)[6]),"=r"((r)[7]), \
          "=r"((r)[8]),"=r"((r)[9]),"=r"((r)[10]),"=r"((r)[11]),"=r"((r)[12]),"=r"((r)[13]),"=r"((r)[14]),"=r"((r)[15]), \
          "=r"((r)[16]),"=r"((r)[17]),"=r"((r)[18]),"=r"((r)[19]),"=r"((r)[20]),"=r"((r)[21]),"=r"((r)[22]),"=r"((r)[23]), \
          "=r"((r)[24]),"=r"((r)[25]),"=r"((r)[26]),"=r"((r)[27]),"=r"((r)[28]),"=r"((r)[29]),"=r"((r)[30]),"=r"((r)[31]) \
        : "r"(ta))
#endif // HAS_TCGEN05

// idesc: dtype=F32(1<<4), atype=BF16(1<<7), btype=BF16(1<<10), N>>3 <<17, M>>4 <<24
#define IDESC_N128 0x8200490u
#define IDESC_N64  0x8100490u

// ---------------- smem layout (bytes), edge kernel ----------------
#define OFF_TMEM  0
#define OFF_MBAR0 16
#define OFF_MBAR1 24
#define OFF_SSEG  32      // 128 ints
#define OFF_BP2   544     // 256 f
#define OFF_BP3   1568    // 64 f
#define OFF_BP1   1824    // 256 f
#define OFF_WP1   2848    // 1024 f
#define OFF_A0    7168    // 32KB: hi 16K + lo 16K
#define OFF_A1    39936
#define OFF_B0    72704   // 64KB: hi 32K + lo 32K
#define OFF_B1    138240
#define EDGE_SMEM 203776

#define NT_EDGE 256

// ---------------- weight prep: transpose + bf16 split ----------------
__global__ void prep_kernel(const float* __restrict__ Wp2, const float* __restrict__ Wp3) {
    int i = blockIdx.x * blockDim.x + threadIdx.x;
    if (i < 256 * 256) {
        int n = i >> 8, k = i & 255;
        float w = Wp2[k * 256 + n];
        __nv_bfloat16 h = __float2bfloat16(w);
        float r = w - __bfloat162float(h);
        g_Wp2T_hi[n * 256 + k] = h;
        g_Wp2T_lo[n * 256 + k] = __float2bfloat16(r);
    }
    if (i < 64 * 256) {
        int n = i >> 8, k = i & 255;
        float w = Wp3[k * 64 + n];
        __nv_bfloat16 h = __float2bfloat16(w);
        float r = w - __bfloat162float(h);
        g_Wp3T_hi[n * 256 + k] = h;
        g_Wp3T_lo[n * 256 + k] = __float2bfloat16(r);
    }
}

__global__ void zero_kernel() {
    const int i = blockIdx.x * blockDim.x + threadIdx.x;
    if (i < N_AG * AGG_STRIDE) g_agg[i] = 0.0f;
}

// ---------------- edge kernel: fused MLP on tcgen05, 256 threads ----------------
__global__ void __launch_bounds__(NT_EDGE, 1) edge_kernel(
    const float* __restrict__ ef, const int* __restrict__ seg,
    const float* __restrict__ Wp1, const float* __restrict__ bp1,
    const float* __restrict__ bp2, const float* __restrict__ bp3,
    const float* __restrict__ Wp2g, const float* __restrict__ Wp3g)
{
    extern __shared__ char sm[];
    const uint32_t smb = smem_u32(sm);
    const int tid = threadIdx.x;
    const int wid = tid >> 5;
    const int e0 = blockIdx.x * 128;
    const int edge = tid & 127;     // each edge handled by 2 threads (col halves)
    const int half = tid >> 7;      // 0: cols [0,32), 1: cols [32,64) of each 64-chunk

    int*   sseg = (int*)(sm + OFF_SSEG);
    float* bp2s = (float*)(sm + OFF_BP2);
    float* bp3s = (float*)(sm + OFF_BP3);
    float* bp1s = (float*)(sm + OFF_BP1);
    float* wp1s = (float*)(sm + OFF_WP1);

#if HAS_TCGEN05
    if (wid == 0) { TC_ALLOC(smb + OFF_TMEM, 512); TC_RELINQ(); }
    if (tid == 0) { MBAR_INIT(smb + OFF_MBAR0, 1); MBAR_INIT(smb + OFF_MBAR1, 1); }
#endif

    const float4 x = ((const float4*)ef)[e0 + edge];
    if (tid < 128) sseg[tid] = seg[e0 + tid];
    wp1s[tid] = Wp1[tid];             wp1s[tid + 256] = Wp1[tid + 256];
    wp1s[tid + 512] = Wp1[tid + 512]; wp1s[tid + 768] = Wp1[tid + 768];
    bp1s[tid] = bp1[tid];
    bp2s[tid] = bp2[tid];
    if (tid < 64) bp3s[tid] = bp3[tid];
    __syncthreads();

    float* h3T = (float*)(sm + OFF_B0);   // [66][132] epilogue staging

#if HAS_TCGEN05
    uint32_t tmem;
    asm volatile("ld.shared.b32 %0, [%1];" : "=r"(tmem) : "r"(smb + OFF_TMEM));
    const uint32_t tD2 = tmem;        // 256 cols
    const uint32_t tD3 = tmem + 256;  // 64 cols
    const uint32_t warp_off = (uint32_t)(wid & 3) << 21;
    int p0 = 0, p1 = 0;

    // ================= layer 2: K=256 in 4 chunks of 64 =================
    for (int kc = 0; kc < 4; kc++) {
        if (kc >= 2) {
            if ((kc & 1) == 0) { MBAR_WAIT(smb + OFF_MBAR0, p0); p0 ^= 1; }
            else               { MBAR_WAIT(smb + OFF_MBAR1, p1); p1 ^= 1; }
        }
        char* A = sm + ((kc & 1) ? OFF_A1 : OFF_A0);
        char* B = sm + ((kc & 1) ? OFF_B1 : OFF_B0);

        // ---- layer 1 on the fly: this thread does 32 of the 64 chunk cols ----
        #pragma unroll
        for (int g = 0; g < 4; g++) {
            const int gg = half * 4 + g;
            uint32_t hi4[4], lo4[4];
            #pragma unroll
            for (int q = 0; q < 4; q++) {
                const int c = kc * 64 + gg * 8 + q * 2;
                float v0 = fmaf(x.x, wp1s[c],       fmaf(x.y, wp1s[256 + c],
                           fmaf(x.z, wp1s[512 + c], fmaf(x.w, wp1s[768 + c], bp1s[c]))));
                float v1 = fmaf(x.x, wp1s[c + 1],       fmaf(x.y, wp1s[256 + c + 1],
                           fmaf(x.z, wp1s[512 + c + 1], fmaf(x.w, wp1s[768 + c + 1], bp1s[c + 1]))));
                v0 = fmaxf(v0, 0.0f); v1 = fmaxf(v1, 0.0f);
                split2(v0, v1, hi4[q], lo4[q]);
            }
            const uint32_t so = swz128(edge * 128 + gg * 16);
            *(uint4*)(A + so)         = make_uint4(hi4[0], hi4[1], hi4[2], hi4[3]);
            *(uint4*)(A + 16384 + so) = make_uint4(lo4[0], lo4[1], lo4[2], lo4[3]);
        }

        // ---- stream Wp2T chunk [256 rows x 64 k] hi+lo ----
        #pragma unroll
        for (int it = 0; it < 8; it++) {
            const int idx = tid + it * NT_EDGE;
            const int n = idx >> 3, sg = idx & 7;
            const uint4 vh = ((const uint4*)(g_Wp2T_hi + n * 256 + kc * 64))[sg];
            const uint4 vl = ((const uint4*)(g_Wp2T_lo + n * 256 + kc * 64))[sg];
            const uint32_t so = swz128(n * 128 + sg * 16);
            *(uint4*)(B + so)         = vh;
            *(uint4*)(B + 32768 + so) = vl;
        }
        FENCE_ASYNC();
        __syncthreads();

        if (tid == 0) {
            const uint64_t dAh = mk_desc(smb + (uint32_t)(A - sm));
            const uint64_t dAl = dAh + 1024;   // +16KB
            const uint64_t dBh = mk_desc(smb + (uint32_t)(B - sm));
            const uint64_t dBl = dBh + 2048;   // +32KB
            #pragma unroll
            for (int s = 0; s < 4; s++) {
                #pragma unroll
                for (int h = 0; h < 2; h++) {
                    const uint32_t d = tD2 + h * 128;
                    const uint64_t bo = (uint64_t)h * 1024 + s * 2;  // +16KB per N-half
                    mma_f16_ss(d, dAh + s * 2, dBh + bo, IDESC_N128, !(kc == 0 && s == 0));
                    mma_f16_ss(d, dAh + s * 2, dBl + bo, IDESC_N128, 1);
                    mma_f16_ss(d, dAl + s * 2, dBh + bo, IDESC_N128, 1);
                }
            }
            TC_COMMIT(smb + ((kc & 1) ? OFF_MBAR1 : OFF_MBAR0));
        }
        __syncthreads();
    }

    // all layer-2 MMAs done
    MBAR_WAIT(smb + OFF_MBAR0, p0); p0 ^= 1;
    MBAR_WAIT(smb + OFF_MBAR1, p1); p1 ^= 1;
    TC_FENCE_AFTER();

    // ================= layer 3: h2 slices -> D3 =================
    // warps 0-3 read cols [i*64, i*64+32), warps 4-7 read [i*64+32, i*64+64)
    for (int i = 0; i < 4; i++) {
        if (i >= 2) {
            if ((i & 1) == 0) { MBAR_WAIT(smb + OFF_MBAR0, p0); p0 ^= 1; }
            else              { MBAR_WAIT(smb + OFF_MBAR1, p1); p1 ^= 1; }
        }
        uint32_t r0[32];
        TC_LD_X32(r0, tD2 + i * 64 + half * 32 + warp_off);
        TC_WAIT_LD();

        char* A2 = sm + ((i & 1) ? OFF_A1 : OFF_A0);
        char* B3 = sm + OFF_B1 + (i & 1) * 16384;   // hi 8K + lo 8K

        #pragma unroll
        for (int g = 0; g < 4; g++) {
            const int gg = half * 4 + g;
            uint32_t hi4[4], lo4[4];
            #pragma unroll
            for (int q = 0; q < 4; q++) {
                const int j = g * 8 + q * 2;
                const int c = i * 64 + half * 32 + j;
                float v0 = fmaxf(__uint_as_float(r0[j])     + bp2s[c],     0.0f);
                float v1 = fmaxf(__uint_as_float(r0[j + 1]) + bp2s[c + 1], 0.0f);
                split2(v0, v1, hi4[q], lo4[q]);
            }
            const uint32_t so = swz128(edge * 128 + gg * 16);
            *(uint4*)(A2 + so)         = make_uint4(hi4[0], hi4[1], hi4[2], hi4[3]);
            *(uint4*)(A2 + 16384 + so) = make_uint4(lo4[0], lo4[1], lo4[2], lo4[3]);
        }

        // Wp3T chunk [64 rows x 64 k] hi+lo
        #pragma unroll
        for (int it = 0; it < 2; it++) {
            const int idx = tid + it * NT_EDGE;
            const int n = idx >> 3, sg = idx & 7;
            const uint4 vh = ((const uint4*)(g_Wp3T_hi + n * 256 + i * 64))[sg];
            const uint4 vl = ((const uint4*)(g_Wp3T_lo + n * 256 + i * 64))[sg];
            const uint32_t so = swz128(n * 128 + sg * 16);
            *(uint4*)(B3 + so)        = vh;
            *(uint4*)(B3 + 8192 + so) = vl;
        }
        FENCE_ASYNC();
        __syncthreads();

        if (tid == 0) {
            const uint64_t dAh = mk_desc(smb + (uint32_t)(A2 - sm));
            const uint64_t dAl = dAh + 1024;  // +16KB
            const uint64_t dBh = mk_desc(smb + (uint32_t)(B3 - sm));
            const uint64_t dBl = dBh + 512;   // +8KB
            #pragma unroll
            for (int s = 0; s < 4; s++) {
                mma_f16_ss(tD3, dAh + s * 2, dBh + s * 2, IDESC_N64, !(i == 0 && s == 0));
                mma_f16_ss(tD3, dAh + s * 2, dBl + s * 2, IDESC_N64, 1);
                mma_f16_ss(tD3, dAl + s * 2, dBh + s * 2, IDESC_N64, 1);
            }
            TC_COMMIT(smb + ((i & 1) ? OFF_MBAR1 : OFF_MBAR0));
        }
        __syncthreads();
    }

    MBAR_WAIT(smb + OFF_MBAR0, p0); p0 ^= 1;
    MBAR_WAIT(smb + OFF_MBAR1, p1); p1 ^= 1;
    TC_FENCE_AFTER();

    // h3 rows into column-major staging (each half-warpgroup does 32 cols)
    {
        uint32_t r0[32];
        TC_LD_X32(r0, tD3 + half * 32 + warp_off);
        TC_WAIT_LD();

        #pragma unroll
        for (int c = 0; c < 32; c++)
            h3T[(half * 32 + c) * 132 + edge] = __uint_as_float(r0[c]) + bp3s[half * 32 + c];
    }
#else
    // ---------- correct scalar fallback (compiled only for non-'a' targets) ----------
    {
        float* hbuf = (float*)(sm + OFF_A0);   // [256][128] k-major
        if (tid < 128) {
            for (int k = 0; k < 256; k++) {
                float v = fmaf(x.x, wp1s[k],       fmaf(x.y, wp1s[256 + k],
                          fmaf(x.z, wp1s[512 + k], fmaf(x.w, wp1s[768 + k], bp1s[k]))));
                hbuf[k * 128 + tid] = fmaxf(v, 0.0f);
            }
            float h3a[64];
            for (int n = 0; n < 64; n++) h3a[n] = bp3s[n];
            for (int kc = 0; kc < 4; kc++) {
                float h2c[64];
                for (int j = 0; j < 64; j++) {
                    const int c = kc * 64 + j;
                    float s = bp2s[c];
                    for (int k = 0; k < 256; k++)
                        s = fmaf(hbuf[k * 128 + tid], Wp2g[k * 256 + c], s);
                    h2c[j] = fmaxf(s, 0.0f);
                }
                for (int j = 0; j < 64; j++) {
                    const int r = kc * 64 + j;
                    for (int n = 0; n < 64; n++)
                        h3a[n] = fmaf(h2c[j], Wp3g[r * 64 + n], h3a[n]);
                }
            }
            for (int c = 0; c < 64; c++)
                h3T[c * 132 + tid] = h3a[c];
        }
    }
#endif

    // ================= epilogue: barrier term + segmented reduce =================
    {
        if (tid < 128) {
            const float px = x.x, py = x.y;
            const float d = sqrtf(px * px + py * py);
            const float s = -1.0f / (d * (d - 0.18f));
            h3T[64 * 132 + tid] = px * s;
            h3T[65 * 132 + tid] = py * s;
        }
        __syncthreads();

        // two parallel scanners: cols 0..65 over edges [0,64) and [64,128)
        const int sc = (tid < 66) ? 0 : ((tid >= 128 && tid < 194) ? 1 : -1);
        if (sc >= 0) {
            const int col = (sc == 0) ? tid : (tid - 128);
            const int eb = sc * 64;
            const float* colp = h3T + col * 132 + eb;
            int cur = sseg[eb];
            float run = 0.0f;
            #pragma unroll 4
            for (int e = 0; e < 64; e++) {
                const int sg = sseg[eb + e];
                if (sg != cur) { atomicAdd(&g_agg[cur * 66 + col], run); run = 0.0f; cur = sg; }
                run += colp[e];
            }
            atomicAdd(&g_agg[cur * 66 + col], run);
        }
    }
    __syncthreads();
#if HAS_TCGEN05
    if (wid == 0) TC_DEALLOC(tmem, 512);
#endif
}

// ---------------- agent kernel (fp32x2 path, arch-portable) ----------------
__device__ __forceinline__ unsigned long long dup2(float a) {
    unsigned long long r;
    asm("mov.b64 %0, {%1, %1};" : "=l"(r) : "f"(a));
    return r;
}
__device__ __forceinline__ unsigned long long pack2(float lo, float hi) {
    unsigned long long r;
    asm("mov.b64 %0, {%1, %2};" : "=l"(r) : "f"(lo), "f"(hi));
    return r;
}
__device__ __forceinline__ void unpack2(unsigned long long v, float& lo, float& hi) {
    asm("mov.b64 {%0, %1}, %2;" : "=f"(lo), "=f"(hi) : "l"(v));
}
__device__ __forceinline__ void fma2(unsigned long long& acc, unsigned long long a, unsigned long long b) {
    asm("fma.rn.f32x2 %0, %1, %2, %0;" : "+l"(acc) : "l"(a), "l"(b));
}

#define AGENT_SMEM_FLOATS (2112 + 8448 + 8448 + 8192 + 512)
#define AGENT_SMEM_BYTES  (AGENT_SMEM_FLOATS * 4)

__global__ void __launch_bounds__(256, 2) agent_kernel(
    const float* __restrict__ Wr1, const float* __restrict__ br1,
    const float* __restrict__ Wr2, const float* __restrict__ br2,
    const float* __restrict__ Wr3, const float* __restrict__ br3,
    float* __restrict__ out)
{
    extern __shared__ float smf[];
    float* g1 = smf;
    float* h2 = g1 + 2112;
    float* r2 = h2 + 8448;
    float* wc = r2 + 8448;
    float* w3 = wc + 8192;

    const int tid = threadIdx.x;
    const int a0 = blockIdx.x * 32;

    #pragma unroll
    for (int i = 0; i < 8; i++) {
        const int idx = tid + i * 256;
        const int e = idx >> 6, k = idx & 63;
        g1[k * 33 + e] = g_agg[(a0 + e) * 66 + k];
    }
    w3[tid] = Wr3[tid];
    w3[tid + 256] = Wr3[tid + 256];
    __syncthreads();

    const int te = tid & 7;
    const int tn = tid >> 3;
    const int el = te * 4;
    const int n0 = tn * 8;

    unsigned long long acc[4][4];

    {   // r1 = relu(agg @ Wr1 + br1), K=64
        const float4 blo = *(const float4*)&br1[n0];
        const float4 bhi = *(const float4*)&br1[n0 + 4];
        const unsigned long long q0 = pack2(blo.x, blo.y), q1 = pack2(blo.z, blo.w);
        const unsigned long long q2 = pack2(bhi.x, bhi.y), q3 = pack2(bhi.z, bhi.w);
        #pragma unroll
        for (int i = 0; i < 4; i++) { acc[i][0]=q0; acc[i][1]=q1; acc[i][2]=q2; acc[i][3]=q3; }

        for (int kc = 0; kc < 2; kc++) {
            __syncthreads();
            const float4* src = (const float4*)(Wr1 + kc * 32 * 256);
            float4* dst = (float4*)wc;
            #pragma unroll
            for (int i = 0; i < 8; i++) dst[tid + i * 256] = src[tid + i * 256];
            __syncthreads();
            #pragma unroll
            for (int k = 0; k < 32; k++) {
                const float* hrow = &g1[(kc * 32 + k) * 33 + el];
                const unsigned long long a0d = dup2(hrow[0]);
                const unsigned long long a1d = dup2(hrow[1]);
                const unsigned long long a2d = dup2(hrow[2]);
                const unsigned long long a3d = dup2(hrow[3]);
                const ulonglong2 u0 = *(const ulonglong2*)&wc[k * 256 + n0];
                const ulonglong2 u1 = *(const ulonglong2*)&wc[k * 256 + n0 + 4];
                fma2(acc[0][0], a0d, u0.x); fma2(acc[0][1], a0d, u0.y);
                fma2(acc[0][2], a0d, u1.x); fma2(acc[0][3], a0d, u1.y);
                fma2(acc[1][0], a1d, u0.x); fma2(acc[1][1], a1d, u0.y);
                fma2(acc[1][2], a1d, u1.x); fma2(acc[1][3], a1d, u1.y);
                fma2(acc[2][0], a2d, u0.x); fma2(acc[2][1], a2d, u0.y);
                fma2(acc[2][2], a2d, u1.x); fma2(acc[2][3], a2d, u1.y);
                fma2(acc[3][0], a3d, u0.x); fma2(acc[3][1], a3d, u0.y);
                fma2(acc[3][2], a3d, u1.x); fma2(acc[3][3], a3d, u1.y);
            }
        }
        #pragma unroll
        for (int i = 0; i < 4; i++)
            #pragma unroll
            for (int j = 0; j < 4; j++) {
                float lo, hi; unpack2(acc[i][j], lo, hi);
                h2[(n0 + 2*j    ) * 33 + el + i] = fmaxf(lo, 0.0f);
                h2[(n0 + 2*j + 1) * 33 + el + i] = fmaxf(hi, 0.0f);
            }
    }

    {   // r2 = relu(r1 @ Wr2 + br2), K=256
        const float4 blo = *(const float4*)&br2[n0];
        const float4 bhi = *(const float4*)&br2[n0 + 4];
        const unsigned long long q0 = pack2(blo.x, blo.y), q1 = pack2(blo.z, blo.w);
        const unsigned long long q2 = pack2(bhi.x, bhi.y), q3 = pack2(bhi.z, bhi.w);
        #pragma unroll
        for (int i = 0; i < 4; i++) { acc[i][0]=q0; acc[i][1]=q1; acc[i][2]=q2; acc[i][3]=q3; }

        for (int kc = 0; kc < 8; kc++) {
            __syncthreads();
            const float4* src = (const float4*)(Wr2 + kc * 32 * 256);
            float4* dst = (float4*)wc;
            #pragma unroll
            for (int i = 0; i < 8; i++) dst[tid + i * 256] = src[tid + i * 256];
            __syncthreads();
            #pragma unroll
            for (int k = 0; k < 32; k++) {
                const float* hrow = &h2[(kc * 32 + k) * 33 + el];
                const unsigned long long a0d = dup2(hrow[0]);
                const unsigned long long a1d = dup2(hrow[1]);
                const unsigned long long a2d = dup2(hrow[2]);
                const unsigned long long a3d = dup2(hrow[3]);
                const ulonglong2 u0 = *(const ulonglong2*)&wc[k * 256 + n0];
                const ulonglong2 u1 = *(const ulonglong2*)&wc[k * 256 + n0 + 4];
                fma2(acc[0][0], a0d, u0.x); fma2(acc[0][1], a0d, u0.y);
                fma2(acc[0][2], a0d, u1.x); fma2(acc[0][3], a0d, u1.y);
                fma2(acc[1][0], a1d, u0.x); fma2(acc[1][1], a1d, u0.y);
                fma2(acc[1][2], a1d, u1.x); fma2(acc[1][3], a1d, u1.y);
                fma2(acc[2][0], a2d, u0.x); fma2(acc[2][1], a2d, u0.y);
                fma2(acc[2][2], a2d, u1.x); fma2(acc[2][3], a2d, u1.y);
                fma2(acc[3][0], a3d, u0.x); fma2(acc[3][1], a3d, u0.y);
                fma2(acc[3][2], a3d, u1.x); fma2(acc[3][3], a3d, u1.y);
            }
        }
        #pragma unroll
        for (int i = 0; i < 4; i++)
            #pragma unroll
            for (int j = 0; j < 4; j++) {
                float lo, hi; unpack2(acc[i][j], lo, hi);
                r2[(n0 + 2*j    ) * 33 + el + i] = fmaxf(lo, 0.0f);
                r2[(n0 + 2*j + 1) * 33 + el + i] = fmaxf(hi, 0.0f);
            }
    }
    __syncthreads();

    if (tid < 64) {
        const int e = tid >> 1, c = tid & 1;
        float sum = br3[c];
        #pragma unroll 8
        for (int k = 0; k < 256; k++)
            sum += r2[k * 33 + e] * w3[k * 2 + c];
        out[(a0 + e) * 2 + c] = sum + g_agg[(a0 + e) * 66 + 64 + c];
    }
}

// ---------------- launch ----------------
extern "C" void kernel_launch(void* const* d_in, const int* in_sizes, int n_in,
                              void* d_out, int out_size) {
    const float* ef  = (const float*)d_in[0];
    const int*   seg = (const int*)  d_in[1];
    const float* Wp1 = (const float*)d_in[2];
    const float* bp1 = (const float*)d_in[3];
    const float* Wp2 = (const float*)d_in[4];
    const float* bp2 = (const float*)d_in[5];
    const float* Wp3 = (const float*)d_in[6];
    const float* bp3 = (const float*)d_in[7];
    const float* Wr1 = (const float*)d_in[8];
    const float* br1 = (const float*)d_in[9];
    const float* Wr2 = (const float*)d_in[10];
    const float* br2 = (const float*)d_in[11];
    const float* Wr3 = (const float*)d_in[12];
    const float* br3 = (const float*)d_in[13];
    float* out = (float*)d_out;

    cudaFuncSetAttribute(edge_kernel,  cudaFuncAttributeMaxDynamicSharedMemorySize, EDGE_SMEM);
    cudaFuncSetAttribute(agent_kernel, cudaFuncAttributeMaxDynamicSharedMemorySize, AGENT_SMEM_BYTES);

    prep_kernel<<<256, 256>>>(Wp2, Wp3);
    zero_kernel<<<(N_AG * AGG_STRIDE + 255) / 256, 256>>>();
    edge_kernel<<<E_TOTAL / 128, NT_EDGE, EDGE_SMEM>>>(ef, seg, Wp1, bp1, bp2, bp3, Wp2, Wp3);
    agent_kernel<<<N_AG / 32, 256, AGENT_SMEM_BYTES>>>(Wr1, br1, Wr2, br2, Wr3, br3, out);
}

// round 6
// speedup vs baseline: 4.5705x; 1.0881x over previous
#include <cuda_runtime.h>
#include <cuda_bf16.h>
#include <stdint.h>

#define E_TOTAL   524288
#define N_AG      16384
#define NTILES    (E_TOTAL / 128)
#define AGG_STRIDE 66   // 64 MLP feats + 2 barrier components

// tcgen05 is an arch-specific ('a') feature: only emit it in the sm_103a/sm_100a pass.
#if defined(__CUDA_ARCH_FEAT_SM103_ALL) || defined(__CUDA_ARCH_FEAT_SM100_ALL) || \
    (defined(__CUDA_ARCH_SPECIFIC__) && (__CUDA_ARCH_SPECIFIC__ >= 1000))
#define HAS_TCGEN05 1
#else
#define HAS_TCGEN05 0
#endif

// ---------------- device scratch (alloc-free rule) ----------------
__device__ float g_agg[N_AG * AGG_STRIDE];
__device__ __nv_bfloat16 g_Wp2T_hi[256 * 256];
__device__ __nv_bfloat16 g_Wp2T_lo[256 * 256];
__device__ __nv_bfloat16 g_Wp3T_hi[64 * 256];
__device__ __nv_bfloat16 g_Wp3T_lo[64 * 256];

// ---------------- common helpers ----------------
__device__ __forceinline__ uint32_t smem_u32(const void* p) {
    uint32_t a;
    asm("{ .reg .u64 t; cvta.to.shared.u64 t, %1; cvt.u32.u64 %0, t; }" : "=r"(a) : "l"(p));
    return a;
}
__device__ __forceinline__ uint32_t swz128(uint32_t off) { return off ^ ((off >> 3) & 0x70); }

// Fast truncation split: hi = top-16 bits (exact bf16), lo = v - hi (exact fp32), truncated.
__device__ __forceinline__ void split2(float v0, float v1, uint32_t& hi, uint32_t& lo) {
    const uint32_t u0 = __float_as_uint(v0), u1 = __float_as_uint(v1);
    hi = __byte_perm(u0, u1, 0x7632);
    const float l0 = v0 - __uint_as_float(u0 & 0xFFFF0000u);
    const float l1 = v1 - __uint_as_float(u1 & 0xFFFF0000u);
    lo = __byte_perm(__float_as_uint(l0), __float_as_uint(l1), 0x7632);
}

#if HAS_TCGEN05
// SW128 K-major smem descriptor (LBO=1, SBO=64, version=1)
__device__ __forceinline__ uint64_t mk_desc(uint32_t addr) {
    const uint64_t base = (uint64_t(2) << 61) | (uint64_t(1) << 46) | (uint64_t(64) << 32) | (uint64_t(1) << 16);
    return base | ((uint64_t)(addr >> 4) & 0x3FFF);
}
__device__ __forceinline__ void mma_f16_ss(uint32_t d, uint64_t a, uint64_t b, uint32_t idesc, uint32_t en) {
    asm volatile(
        "{\n\t.reg .pred p;\n\tsetp.ne.u32 p, %5, 0;\n\t"
        "tcgen05.mma.cta_group::1.kind::f16 [%0], %1, %2, %3, {%4,%4,%4,%4}, p;\n\t}"
        :: "r"(d), "l"(a), "l"(b), "r"(idesc), "r"(0u), "r"(en) : "memory");
}
#define TC_ALLOC(sa, n)   asm volatile("tcgen05.alloc.cta_group::1.sync.aligned.shared::cta.b32 [%0], %1;" :: "r"(sa), "r"(n) : "memory")
#define TC_RELINQ()       asm volatile("tcgen05.relinquish_alloc_permit.cta_group::1.sync.aligned;")
#define TC_DEALLOC(t, n)  asm volatile("tcgen05.dealloc.cta_group::1.sync.aligned.b32 %0, %1;" :: "r"(t), "r"(n))
#define TC_COMMIT(mb)     asm volatile("tcgen05.commit.cta_group::1.mbarrier::arrive::one.shared::cluster.b64 [%0];" :: "r"(mb) : "memory")
#define TC_FENCE_AFTER()  asm volatile("tcgen05.fence::after_thread_sync;" ::: "memory")
#define TC_FENCE_BEFORE() asm volatile("tcgen05.fence::before_thread_sync;" ::: "memory")
#define TC_WAIT_LD()      asm volatile("tcgen05.wait::ld.sync.aligned;" ::: "memory")
#define FENCE_ASYNC()     asm volatile("fence.proxy.async.shared::cta;" ::: "memory")
#define MBAR_INIT(mb, c)  asm volatile("mbarrier.init.shared.b64 [%0], %1;" :: "r"(mb), "r"(c) : "memory")

#define MBAR_WAIT(mb, par) do { \
    uint32_t _m = (mb); uint32_t _p = (par); uint32_t _d; \
    asm volatile("{\n\t.reg .pred p;\n\t" \
        "mbarrier.try_wait.parity.acquire.cta.shared::cta.b64 p, [%1], %2;\n\t" \
        "selp.b32 %0, 1, 0, p;\n\t}" : "=r"(_d) : "r"(_m), "r"(_p) : "memory"); \
    if (!_d) { \
        asm volatile("{\n\t.reg .pred P1;\n\t" \
            "WL_%=:\n\t" \
            "mbarrier.try_wait.parity.acquire.cta.shared::cta.b64 P1, [%0], %1, 0x989680;\n\t" \
            "@P1 bra.uni WD_%=;\n\t" \
            "bra.uni WL_%=;\n\t" \
            "WD_%=:\n\t}" :: "r"(_m), "r"(_p) : "memory"); \
    } \
} while (0)

#define TC_LD_X32(r, ta) \
    asm volatile("tcgen05.ld.sync.aligned.32x32b.x32.b32 " \
        "{%0,%1,%2,%3,%4,%5,%6,%7,%8,%9,%10,%11,%12,%13,%14,%15," \
        "%16,%17,%18,%19,%20,%21,%22,%23,%24,%25,%26,%27,%28,%29,%30,%31}, [%32];" \
        : "=r"((r)[0]),"=r"((r)[1]),"=r"((r)[2]),"=r"((r)[3]),"=r"((r)[4]),"=r"((r)[5]),"=r"((r)[6]),"=r"((r)[7]), \
          "=r"((r)[8]),"=r"((r)[9]),"=r"((r)[10]),"=r"((r)[11]),"=r"((r)[12]),"=r"((r)[13]),"=r"((r)[14]),"=r"((r)[15]), \
          "=r"((r)[16]),"=r"((r)[17]),"=r"((r)[18]),"=r"((r)[19]),"=r"((r)[20]),"=r"((r)[21]),"=r"((r)[22]),"=r"((r)[23]), \
          "=r"((r)[24]),"=r"((r)[25]),"=r"((r)[26]),"=r"((r)[27]),"=r"((r)[28]),"=r"((r)[29]),"=r"((r)[30]),"=r"((r)[31]) \
        : "r"(ta))
#endif // HAS_TCGEN05

// idesc: dtype=F32(1<<4), atype=BF16(1<<7), btype=BF16(1<<10), N>>3 <<17, M>>4 <<24
#define IDESC_N128 0x8200490u
#define IDESC_N64  0x8100490u

// ---------------- smem layout (bytes), edge kernel ----------------
#define OFF_TMEM  0
#define OFF_MBAR0 16
#define OFF_MBAR1 24
#define OFF_SSEG  32       // 2 x 128 ints (ping-pong) = 1024B
#define OFF_BP2   1056     // 256 f
#define OFF_BP3   2080     // 64 f
#define OFF_BP1   2336     // 256 f
#define OFF_WP1   3360     // 1024 f
#define OFF_A0    8192     // 32KB: hi 16K + lo 16K
#define OFF_A1    40960
#define OFF_B0    73728    // 64KB: hi 32K + lo 32K   (h3T staging reuses this)
#define OFF_B1    139264
#define EDGE_SMEM 204800

#define NT_EDGE 256
#define NCTA_EDGE 148

// ---------------- weight prep: transpose + bf16 split ----------------
__global__ void prep_kernel(const float* __restrict__ Wp2, const float* __restrict__ Wp3) {
    int i = blockIdx.x * blockDim.x + threadIdx.x;
    if (i < 256 * 256) {
        int n = i >> 8, k = i & 255;
        float w = Wp2[k * 256 + n];
        __nv_bfloat16 h = __float2bfloat16(w);
        float r = w - __bfloat162float(h);
        g_Wp2T_hi[n * 256 + k] = h;
        g_Wp2T_lo[n * 256 + k] = __float2bfloat16(r);
    }
    if (i < 64 * 256) {
        int n = i >> 8, k = i & 255;
        float w = Wp3[k * 64 + n];
        __nv_bfloat16 h = __float2bfloat16(w);
        float r = w - __bfloat162float(h);
        g_Wp3T_hi[n * 256 + k] = h;
        g_Wp3T_lo[n * 256 + k] = __float2bfloat16(r);
    }
}

__global__ void zero_kernel() {
    const int i = blockIdx.x * blockDim.x + threadIdx.x;
    if (i < N_AG * AGG_STRIDE) g_agg[i] = 0.0f;
}

// barrier term + segmented-scan epilogue (h3T rows 0..63 must already be written)
__device__ __forceinline__ void do_epilogue(float* h3T, const int* ss, float px, float py, int tid) {
    if (tid < 128) {
        const float d = sqrtf(px * px + py * py);
        const float s = -1.0f / (d * (d - 0.18f));
        h3T[64 * 132 + tid] = px * s;
        h3T[65 * 132 + tid] = py * s;
    }
    __syncthreads();
    const int sc = (tid < 66) ? 0 : ((tid >= 128 && tid < 194) ? 1 : -1);
    if (sc >= 0) {
        const int col = (sc == 0) ? tid : (tid - 128);
        const int eb = sc * 64;
        const float* colp = h3T + col * 132 + eb;
        int cur = ss[eb];
        float run = 0.0f;
        #pragma unroll 4
        for (int e = 0; e < 64; e++) {
            const int sg = ss[eb + e];
            if (sg != cur) { atomicAdd(&g_agg[cur * 66 + col], run); run = 0.0f; cur = sg; }
            run += colp[e];
        }
        atomicAdd(&g_agg[cur * 66 + col], run);
    }
    __syncthreads();
}

// ---------------- edge kernel: persistent, fused MLP on tcgen05 ----------------
__global__ void __launch_bounds__(NT_EDGE, 1) edge_kernel(
    const float* __restrict__ ef, const int* __restrict__ seg,
    const float* __restrict__ Wp1, const float* __restrict__ bp1,
    const float* __restrict__ bp2, const float* __restrict__ bp3,
    const float* __restrict__ Wp2g, const float* __restrict__ Wp3g)
{
    extern __shared__ char sm[];
    const uint32_t smb = smem_u32(sm);
    const int tid = threadIdx.x;
    const int wid = tid >> 5;
    const int edge = tid & 127;     // each edge handled by 2 threads (col halves)
    const int half = tid >> 7;      // 0: cols [0,32), 1: cols [32,64) of each 64-chunk

    int*   sbuf = (int*)(sm + OFF_SSEG);       // 2 x 128
    float* bp2s = (float*)(sm + OFF_BP2);
    float* bp3s = (float*)(sm + OFF_BP3);
    float* bp1s = (float*)(sm + OFF_BP1);
    float* wp1s = (float*)(sm + OFF_WP1);
    float* h3T  = (float*)(sm + OFF_B0);       // [66][132] epilogue staging

#if HAS_TCGEN05
    if (wid == 0) { TC_ALLOC(smb + OFF_TMEM, 512); TC_RELINQ(); }
    if (tid == 0) { MBAR_INIT(smb + OFF_MBAR0, 1); MBAR_INIT(smb + OFF_MBAR1, 1); }
#endif

    // invariants
    wp1s[tid] = Wp1[tid];             wp1s[tid + 256] = Wp1[tid + 256];
    wp1s[tid + 512] = Wp1[tid + 512]; wp1s[tid + 768] = Wp1[tid + 768];
    bp1s[tid] = bp1[tid];
    bp2s[tid] = bp2[tid];
    if (tid < 64) bp3s[tid] = bp3[tid];
    __syncthreads();

#if HAS_TCGEN05
    uint32_t tmem;
    asm volatile("ld.shared.b32 %0, [%1];" : "=r"(tmem) : "r"(smb + OFF_TMEM));
    const uint32_t tD2 = tmem;        // 256 cols
    const uint32_t tD3 = tmem + 256;  // 64 cols
    const uint32_t warp_off = (uint32_t)(wid & 3) << 21;
    int par0 = 0, par1 = 0, pend0 = 0, pend1 = 0;

#define WAIT_BUF0() do { if (pend0) { MBAR_WAIT(smb + OFF_MBAR0, par0); par0 ^= 1; pend0 = 0; } } while (0)
#define WAIT_BUF1() do { if (pend1) { MBAR_WAIT(smb + OFF_MBAR1, par1); par1 ^= 1; pend1 = 0; } } while (0)

    float4 xcur = make_float4(0.f, 0.f, 0.f, 0.f), xprev;
    int cnt = 0;

    for (int tile = blockIdx.x; tile < NTILES; tile += gridDim.x, cnt++) {
        const int e0 = tile * 128;
        const int sb = cnt & 1;
        xprev = xcur;
        xcur = ((const float4*)ef)[e0 + edge];
        if (tid < 128) sbuf[sb * 128 + tid] = seg[e0 + tid];

        // ================= layer 2: K=256 in 4 chunks of 64 =================
        for (int kc = 0; kc < 4; kc++) {
            if (kc & 1) WAIT_BUF1(); else WAIT_BUF0();
            char* A = sm + ((kc & 1) ? OFF_A1 : OFF_A0);
            char* B = sm + ((kc & 1) ? OFF_B1 : OFF_B0);

            // layer 1 on the fly: this thread does 32 of the 64 chunk cols
            #pragma unroll
            for (int g = 0; g < 4; g++) {
                const int gg = half * 4 + g;
                uint32_t hi4[4], lo4[4];
                #pragma unroll
                for (int q = 0; q < 4; q++) {
                    const int c = kc * 64 + gg * 8 + q * 2;
                    float v0 = fmaf(xcur.x, wp1s[c],       fmaf(xcur.y, wp1s[256 + c],
                               fmaf(xcur.z, wp1s[512 + c], fmaf(xcur.w, wp1s[768 + c], bp1s[c]))));
                    float v1 = fmaf(xcur.x, wp1s[c + 1],       fmaf(xcur.y, wp1s[256 + c + 1],
                               fmaf(xcur.z, wp1s[512 + c + 1], fmaf(xcur.w, wp1s[768 + c + 1], bp1s[c + 1]))));
                    v0 = fmaxf(v0, 0.0f); v1 = fmaxf(v1, 0.0f);
                    split2(v0, v1, hi4[q], lo4[q]);
                }
                const uint32_t so = swz128(edge * 128 + gg * 16);
                *(uint4*)(A + so)         = make_uint4(hi4[0], hi4[1], hi4[2], hi4[3]);
                *(uint4*)(A + 16384 + so) = make_uint4(lo4[0], lo4[1], lo4[2], lo4[3]);
            }

            // stream Wp2T chunk [256 rows x 64 k] hi+lo
            #pragma unroll
            for (int it = 0; it < 8; it++) {
                const int idx = tid + it * NT_EDGE;
                const int n = idx >> 3, sg = idx & 7;
                const uint4 vh = ((const uint4*)(g_Wp2T_hi + n * 256 + kc * 64))[sg];
                const uint4 vl = ((const uint4*)(g_Wp2T_lo + n * 256 + kc * 64))[sg];
                const uint32_t so = swz128(n * 128 + sg * 16);
                *(uint4*)(B + so)         = vh;
                *(uint4*)(B + 32768 + so) = vl;
            }
            FENCE_ASYNC();
            __syncthreads();

            if (tid == 0) {
                const uint64_t dAh = mk_desc(smb + (uint32_t)(A - sm));
                const uint64_t dAl = dAh + 1024;   // +16KB
                const uint64_t dBh = mk_desc(smb + (uint32_t)(B - sm));
                const uint64_t dBl = dBh + 2048;   // +32KB
                #pragma unroll
                for (int s = 0; s < 4; s++) {
                    #pragma unroll
                    for (int h = 0; h < 2; h++) {
                        const uint32_t d = tD2 + h * 128;
                        const uint64_t bo = (uint64_t)h * 1024 + s * 2;
                        mma_f16_ss(d, dAh + s * 2, dBh + bo, IDESC_N128, !(kc == 0 && s == 0));
                        mma_f16_ss(d, dAh + s * 2, dBl + bo, IDESC_N128, 1);
                        mma_f16_ss(d, dAl + s * 2, dBh + bo, IDESC_N128, 1);
                    }
                }
                TC_COMMIT(smb + ((kc & 1) ? OFF_MBAR1 : OFF_MBAR0));
            }
            if (kc & 1) pend1 = 1; else pend0 = 1;
        }

        // drain layer-2 MMAs (required before reading D2)
        WAIT_BUF0();
        WAIT_BUF1();
        TC_FENCE_AFTER();

        // -------- epilogue of PREVIOUS tile fills the drain bubble --------
        if (cnt > 0) {
            uint32_t r0[32];
            TC_LD_X32(r0, tD3 + half * 32 + warp_off);
            TC_WAIT_LD();
            TC_FENCE_BEFORE();
            #pragma unroll
            for (int c = 0; c < 32; c++)
                h3T[(half * 32 + c) * 132 + edge] = __uint_as_float(r0[c]) + bp3s[half * 32 + c];
            do_epilogue(h3T, sbuf + (sb ^ 1) * 128, xprev.x, xprev.y, tid);
        }

        // ================= layer 3: h2 slices -> D3 =================
        for (int i = 0; i < 4; i++) {
            if (i & 1) WAIT_BUF1(); else WAIT_BUF0();
            uint32_t r0[32];
            TC_LD_X32(r0, tD2 + i * 64 + half * 32 + warp_off);
            TC_WAIT_LD();

            char* A2 = sm + ((i & 1) ? OFF_A1 : OFF_A0);
            char* B3 = sm + OFF_B1 + (i & 1) * 16384;   // hi 8K + lo 8K

            #pragma unroll
            for (int g = 0; g < 4; g++) {
                const int gg = half * 4 + g;
                uint32_t hi4[4], lo4[4];
                #pragma unroll
                for (int q = 0; q < 4; q++) {
                    const int j = g * 8 + q * 2;
                    const int c = i * 64 + half * 32 + j;
                    float v0 = fmaxf(__uint_as_float(r0[j])     + bp2s[c],     0.0f);
                    float v1 = fmaxf(__uint_as_float(r0[j + 1]) + bp2s[c + 1], 0.0f);
                    split2(v0, v1, hi4[q], lo4[q]);
                }
                const uint32_t so = swz128(edge * 128 + gg * 16);
                *(uint4*)(A2 + so)         = make_uint4(hi4[0], hi4[1], hi4[2], hi4[3]);
                *(uint4*)(A2 + 16384 + so) = make_uint4(lo4[0], lo4[1], lo4[2], lo4[3]);
            }

            // Wp3T chunk [64 rows x 64 k] hi+lo
            #pragma unroll
            for (int it = 0; it < 2; it++) {
                const int idx = tid + it * NT_EDGE;
                const int n = idx >> 3, sg = idx & 7;
                const uint4 vh = ((const uint4*)(g_Wp3T_hi + n * 256 + i * 64))[sg];
                const uint4 vl = ((const uint4*)(g_Wp3T_lo + n * 256 + i * 64))[sg];
                const uint32_t so = swz128(n * 128 + sg * 16);
                *(uint4*)(B3 + so)        = vh;
                *(uint4*)(B3 + 8192 + so) = vl;
            }
            FENCE_ASYNC();
            TC_FENCE_BEFORE();
            __syncthreads();

            if (tid == 0) {
                TC_FENCE_AFTER();
                const uint64_t dAh = mk_desc(smb + (uint32_t)(A2 - sm));
                const uint64_t dAl = dAh + 1024;  // +16KB
                const uint64_t dBh = mk_desc(smb + (uint32_t)(B3 - sm));
                const uint64_t dBl = dBh + 512;   // +8KB
                #pragma unroll
                for (int s = 0; s < 4; s++) {
                    mma_f16_ss(tD3, dAh + s * 2, dBh + s * 2, IDESC_N64, !(i == 0 && s == 0));
                    mma_f16_ss(tD3, dAh + s * 2, dBl + s * 2, IDESC_N64, 1);
                    mma_f16_ss(tD3, dAl + s * 2, dBh + s * 2, IDESC_N64, 1);
                }
                TC_COMMIT(smb + ((i & 1) ? OFF_MBAR1 : OFF_MBAR0));
            }
            if (i & 1) pend1 = 1; else pend0 = 1;
        }
    }

    // -------- final drain + epilogue of the last tile --------
    WAIT_BUF0();
    WAIT_BUF1();
    if (cnt > 0) {
        TC_FENCE_AFTER();
        uint32_t r0[32];
        TC_LD_X32(r0, tD3 + half * 32 + warp_off);
        TC_WAIT_LD();
        TC_FENCE_BEFORE();
        #pragma unroll
        for (int c = 0; c < 32; c++)
            h3T[(half * 32 + c) * 132 + edge] = __uint_as_float(r0[c]) + bp3s[half * 32 + c];
        do_epilogue(h3T, sbuf + ((cnt - 1) & 1) * 128, xcur.x, xcur.y, tid);
    }
    __syncthreads();
    if (wid == 0) TC_DEALLOC(tmem, 512);
#undef WAIT_BUF0
#undef WAIT_BUF1
#else
    // ---------- correct scalar fallback (compiled only for non-'a' targets) ----------
    for (int tile = blockIdx.x; tile < NTILES; tile += gridDim.x) {
        const int e0 = tile * 128;
        const float4 x = ((const float4*)ef)[e0 + edge];
        if (tid < 128) sbuf[tid] = seg[e0 + tid];
        __syncthreads();
        if (tid < 128) {
            float* hbuf = (float*)(sm + OFF_A0);   // [256][128] k-major
            for (int k = 0; k < 256; k++) {
                float v = fmaf(x.x, wp1s[k],       fmaf(x.y, wp1s[256 + k],
                          fmaf(x.z, wp1s[512 + k], fmaf(x.w, wp1s[768 + k], bp1s[k]))));
                hbuf[k * 128 + tid] = fmaxf(v, 0.0f);
            }
            float h3a[64];
            for (int n = 0; n < 64; n++) h3a[n] = bp3s[n];
            for (int kc = 0; kc < 4; kc++) {
                float h2c[64];
                for (int j = 0; j < 64; j++) {
                    const int c = kc * 64 + j;
                    float s = bp2s[c];
                    for (int k = 0; k < 256; k++)
                        s = fmaf(hbuf[k * 128 + tid], Wp2g[k * 256 + c], s);
                    h2c[j] = fmaxf(s, 0.0f);
                }
                for (int j = 0; j < 64; j++) {
                    const int r = kc * 64 + j;
                    for (int n = 0; n < 64; n++)
                        h3a[n] = fmaf(h2c[j], Wp3g[r * 64 + n], h3a[n]);
                }
            }
            for (int c = 0; c < 64; c++)
                h3T[c * 132 + tid] = h3a[c];
        }
        __syncthreads();
        do_epilogue(h3T, sbuf, x.x, x.y, tid);
        __syncthreads();
    }
#endif
}

// ---------------- agent kernel (fp32x2 path, arch-portable) ----------------
__device__ __forceinline__ unsigned long long dup2(float a) {
    unsigned long long r;
    asm("mov.b64 %0, {%1, %1};" : "=l"(r) : "f"(a));
    return r;
}
__device__ __forceinline__ unsigned long long pack2(float lo, float hi) {
    unsigned long long r;
    asm("mov.b64 %0, {%1, %2};" : "=l"(r) : "f"(lo), "f"(hi));
    return r;
}
__device__ __forceinline__ void unpack2(unsigned long long v, float& lo, float& hi) {
    asm("mov.b64 {%0, %1}, %2;" : "=f"(lo), "=f"(hi) : "l"(v));
}
__device__ __forceinline__ void fma2(unsigned long long& acc, unsigned long long a, unsigned long long b) {
    asm("fma.rn.f32x2 %0, %1, %2, %0;" : "+l"(acc) : "l"(a), "l"(b));
}

#define AGENT_SMEM_FLOATS (2112 + 8448 + 8448 + 8192 + 512)
#define AGENT_SMEM_BYTES  (AGENT_SMEM_FLOATS * 4)

__global__ void __launch_bounds__(256, 2) agent_kernel(
    const float* __restrict__ Wr1, const float* __restrict__ br1,
    const float* __restrict__ Wr2, const float* __restrict__ br2,
    const float* __restrict__ Wr3, const float* __restrict__ br3,
    float* __restrict__ out)
{
    extern __shared__ float smf[];
    float* g1 = smf;
    float* h2 = g1 + 2112;
    float* r2 = h2 + 8448;
    float* wc = r2 + 8448;
    float* w3 = wc + 8192;

    const int tid = threadIdx.x;
    const int a0 = blockIdx.x * 32;

    #pragma unroll
    for (int i = 0; i < 8; i++) {
        const int idx = tid + i * 256;
        const int e = idx >> 6, k = idx & 63;
        g1[k * 33 + e] = g_agg[(a0 + e) * 66 + k];
    }
    w3[tid] = Wr3[tid];
    w3[tid + 256] = Wr3[tid + 256];
    __syncthreads();

    const int te = tid & 7;
    const int tn = tid >> 3;
    const int el = te * 4;
    const int n0 = tn * 8;

    unsigned long long acc[4][4];

    {   // r1 = relu(agg @ Wr1 + br1), K=64
        const float4 blo = *(const float4*)&br1[n0];
        const float4 bhi = *(const float4*)&br1[n0 + 4];
        const unsigned long long q0 = pack2(blo.x, blo.y), q1 = pack2(blo.z, blo.w);
        const unsigned long long q2 = pack2(bhi.x, bhi.y), q3 = pack2(bhi.z, bhi.w);
        #pragma unroll
        for (int i = 0; i < 4; i++) { acc[i][0]=q0; acc[i][1]=q1; acc[i][2]=q2; acc[i][3]=q3; }

        for (int kc = 0; kc < 2; kc++) {
            __syncthreads();
            const float4* src = (const float4*)(Wr1 + kc * 32 * 256);
            float4* dst = (float4*)wc;
            #pragma unroll
            for (int i = 0; i < 8; i++) dst[tid + i * 256] = src[tid + i * 256];
            __syncthreads();
            #pragma unroll
            for (int k = 0; k < 32; k++) {
                const float* hrow = &g1[(kc * 32 + k) * 33 + el];
                const unsigned long long a0d = dup2(hrow[0]);
                const unsigned long long a1d = dup2(hrow[1]);
                const unsigned long long a2d = dup2(hrow[2]);
                const unsigned long long a3d = dup2(hrow[3]);
                const ulonglong2 u0 = *(const ulonglong2*)&wc[k * 256 + n0];
                const ulonglong2 u1 = *(const ulonglong2*)&wc[k * 256 + n0 + 4];
                fma2(acc[0][0], a0d, u0.x); fma2(acc[0][1], a0d, u0.y);
                fma2(acc[0][2], a0d, u1.x); fma2(acc[0][3], a0d, u1.y);
                fma2(acc[1][0], a1d, u0.x); fma2(acc[1][1], a1d, u0.y);
                fma2(acc[1][2], a1d, u1.x); fma2(acc[1][3], a1d, u1.y);
                fma2(acc[2][0], a2d, u0.x); fma2(acc[2][1], a2d, u0.y);
                fma2(acc[2][2], a2d, u1.x); fma2(acc[2][3], a2d, u1.y);
                fma2(acc[3][0], a3d, u0.x); fma2(acc[3][1], a3d, u0.y);
                fma2(acc[3][2], a3d, u1.x); fma2(acc[3][3], a3d, u1.y);
            }
        }
        #pragma unroll
        for (int i = 0; i < 4; i++)
            #pragma unroll
            for (int j = 0; j < 4; j++) {
                float lo, hi; unpack2(acc[i][j], lo, hi);
                h2[(n0 + 2*j    ) * 33 + el + i] = fmaxf(lo, 0.0f);
                h2[(n0 + 2*j + 1) * 33 + el + i] = fmaxf(hi, 0.0f);
            }
    }

    {   // r2 = relu(r1 @ Wr2 + br2), K=256
        const float4 blo = *(const float4*)&br2[n0];
        const float4 bhi = *(const float4*)&br2[n0 + 4];
        const unsigned long long q0 = pack2(blo.x, blo.y), q1 = pack2(blo.z, blo.w);
        const unsigned long long q2 = pack2(bhi.x, bhi.y), q3 = pack2(bhi.z, bhi.w);
        #pragma unroll
        for (int i = 0; i < 4; i++) { acc[i][0]=q0; acc[i][1]=q1; acc[i][2]=q2; acc[i][3]=q3; }

        for (int kc = 0; kc < 8; kc++) {
            __syncthreads();
            const float4* src = (const float4*)(Wr2 + kc * 32 * 256);
            float4* dst = (float4*)wc;
            #pragma unroll
            for (int i = 0; i < 8; i++) dst[tid + i * 256] = src[tid + i * 256];
            __syncthreads();
            #pragma unroll
            for (int k = 0; k < 32; k++) {
                const float* hrow = &h2[(kc * 32 + k) * 33 + el];
                const unsigned long long a0d = dup2(hrow[0]);
                const unsigned long long a1d = dup2(hrow[1]);
                const unsigned long long a2d = dup2(hrow[2]);
                const unsigned long long a3d = dup2(hrow[3]);
                const ulonglong2 u0 = *(const ulonglong2*)&wc[k * 256 + n0];
                const ulonglong2 u1 = *(const ulonglong2*)&wc[k * 256 + n0 + 4];
                fma2(acc[0][0], a0d, u0.x); fma2(acc[0][1], a0d, u0.y);
                fma2(acc[0][2], a0d, u1.x); fma2(acc[0][3], a0d, u1.y);
                fma2(acc[1][0], a1d, u0.x); fma2(acc[1][1], a1d, u0.y);
                fma2(acc[1][2], a1d, u1.x); fma2(acc[1][3], a1d, u1.y);
                fma2(acc[2][0], a2d, u0.x); fma2(acc[2][1], a2d, u0.y);
                fma2(acc[2][2], a2d, u1.x); fma2(acc[2][3], a2d, u1.y);
                fma2(acc[3][0], a3d, u0.x); fma2(acc[3][1], a3d, u0.y);
                fma2(acc[3][2], a3d, u1.x); fma2(acc[3][3], a3d, u1.y);
            }
        }
        #pragma unroll
        for (int i = 0; i < 4; i++)
            #pragma unroll
            for (int j = 0; j < 4; j++) {
                float lo, hi; unpack2(acc[i][j], lo, hi);
                r2[(n0 + 2*j    ) * 33 + el + i] = fmaxf(lo, 0.0f);
                r2[(n0 + 2*j + 1) * 33 + el + i] = fmaxf(hi, 0.0f);
            }
    }
    __syncthreads();

    if (tid < 64) {
        const int e = tid >> 1, c = tid & 1;
        float sum = br3[c];
        #pragma unroll 8
        for (int k = 0; k < 256; k++)
            sum += r2[k * 33 + e] * w3[k * 2 + c];
        out[(a0 + e) * 2 + c] = sum + g_agg[(a0 + e) * 66 + 64 + c];
    }
}

// ---------------- launch ----------------
extern "C" void kernel_launch(void* const* d_in, const int* in_sizes, int n_in,
                              void* d_out, int out_size) {
    const float* ef  = (const float*)d_in[0];
    const int*   seg = (const int*)  d_in[1];
    const float* Wp1 = (const float*)d_in[2];
    const float* bp1 = (const float*)d_in[3];
    const float* Wp2 = (const float*)d_in[4];
    const float* bp2 = (const float*)d_in[5];
    const float* Wp3 = (const float*)d_in[6];
    const float* bp3 = (const float*)d_in[7];
    const float* Wr1 = (const float*)d_in[8];
    const float* br1 = (const float*)d_in[9];
    const float* Wr2 = (const float*)d_in[10];
    const float* br2 = (const float*)d_in[11];
    const float* Wr3 = (const float*)d_in[12];
    const float* br3 = (const float*)d_in[13];
    float* out = (float*)d_out;

    cudaFuncSetAttribute(edge_kernel,  cudaFuncAttributeMaxDynamicSharedMemorySize, EDGE_SMEM);
    cudaFuncSetAttribute(agent_kernel, cudaFuncAttributeMaxDynamicSharedMemorySize, AGENT_SMEM_BYTES);

    prep_kernel<<<256, 256>>>(Wp2, Wp3);
    zero_kernel<<<(N_AG * AGG_STRIDE + 255) / 256, 256>>>();
    edge_kernel<<<NCTA_EDGE, NT_EDGE, EDGE_SMEM>>>(ef, seg, Wp1, bp1, bp2, bp3, Wp2, Wp3);
    agent_kernel<<<N_AG / 32, 256, AGENT_SMEM_BYTES>>>(Wr1, br1, Wr2, br2, Wr3, br3, out);
}

// round 7
// speedup vs baseline: 4.7954x; 1.0492x over previous
#include <cuda_runtime.h>
#include <cuda_bf16.h>
#include <stdint.h>

#define E_TOTAL   524288
#define N_AG      16384
#define NTILES    (E_TOTAL / 128)
#define AGG_STRIDE 66   // 64 MLP feats + 2 barrier components

// tcgen05 is an arch-specific ('a') feature: only emit it in the sm_103a/sm_100a pass.
#if defined(__CUDA_ARCH_FEAT_SM103_ALL) || defined(__CUDA_ARCH_FEAT_SM100_ALL) || \
    (defined(__CUDA_ARCH_SPECIFIC__) && (__CUDA_ARCH_SPECIFIC__ >= 1000))
#define HAS_TCGEN05 1
#else
#define HAS_TCGEN05 0
#endif

// ---------------- device scratch (alloc-free rule) ----------------
__device__ float g_agg[N_AG * AGG_STRIDE];
// Weight chunks pre-swizzled (SW128) into their exact SMEM image:
// W2S: 4 chunks x [256 rows x 128B] = 32KB/chunk; W3S: 4 chunks x [64 rows x 128B] = 8KB/chunk
__device__ uint4 g_W2S_hi[8192];   // 131072 B
__device__ uint4 g_W2S_lo[8192];
__device__ uint4 g_W3S_hi[2048];   // 32768 B
__device__ uint4 g_W3S_lo[2048];

// ---------------- common helpers ----------------
__device__ __forceinline__ uint32_t smem_u32(const void* p) {
    uint32_t a;
    asm("{ .reg .u64 t; cvta.to.shared.u64 t, %1; cvt.u32.u64 %0, t; }" : "=r"(a) : "l"(p));
    return a;
}
__device__ __forceinline__ uint32_t swz128(uint32_t off) { return off ^ ((off >> 3) & 0x70); }

// Fast truncation split: hi = top-16 bits (exact bf16), lo = v - hi (exact fp32), truncated.
__device__ __forceinline__ void split2(float v0, float v1, uint32_t& hi, uint32_t& lo) {
    const uint32_t u0 = __float_as_uint(v0), u1 = __float_as_uint(v1);
    hi = __byte_perm(u0, u1, 0x7632);
    const float l0 = v0 - __uint_as_float(u0 & 0xFFFF0000u);
    const float l1 = v1 - __uint_as_float(u1 & 0xFFFF0000u);
    lo = __byte_perm(__float_as_uint(l0), __float_as_uint(l1), 0x7632);
}

#if HAS_TCGEN05
// SW128 K-major smem descriptor (LBO=1, SBO=64, version=1)
__device__ __forceinline__ uint64_t mk_desc(uint32_t addr) {
    const uint64_t base = (uint64_t(2) << 61) | (uint64_t(1) << 46) | (uint64_t(64) << 32) | (uint64_t(1) << 16);
    return base | ((uint64_t)(addr >> 4) & 0x3FFF);
}
__device__ __forceinline__ void mma_f16_ss(uint32_t d, uint64_t a, uint64_t b, uint32_t idesc, uint32_t en) {
    asm volatile(
        "{\n\t.reg .pred p;\n\tsetp.ne.u32 p, %5, 0;\n\t"
        "tcgen05.mma.cta_group::1.kind::f16 [%0], %1, %2, %3, {%4,%4,%4,%4}, p;\n\t}"
        :: "r"(d), "l"(a), "l"(b), "r"(idesc), "r"(0u), "r"(en) : "memory");
}
#define TC_ALLOC(sa, n)   asm volatile("tcgen05.alloc.cta_group::1.sync.aligned.shared::cta.b32 [%0], %1;" :: "r"(sa), "r"(n) : "memory")
#define TC_RELINQ()       asm volatile("tcgen05.relinquish_alloc_permit.cta_group::1.sync.aligned;")
#define TC_DEALLOC(t, n)  asm volatile("tcgen05.dealloc.cta_group::1.sync.aligned.b32 %0, %1;" :: "r"(t), "r"(n))
#define TC_COMMIT(mb)     asm volatile("tcgen05.commit.cta_group::1.mbarrier::arrive::one.shared::cluster.b64 [%0];" :: "r"(mb) : "memory")
#define TC_FENCE_AFTER()  asm volatile("tcgen05.fence::after_thread_sync;" ::: "memory")
#define TC_FENCE_BEFORE() asm volatile("tcgen05.fence::before_thread_sync;" ::: "memory")
#define TC_WAIT_LD()      asm volatile("tcgen05.wait::ld.sync.aligned;" ::: "memory")
#define FENCE_ASYNC()     asm volatile("fence.proxy.async.shared::cta;" ::: "memory")
#define MBAR_INIT(mb, c)  asm volatile("mbarrier.init.shared.b64 [%0], %1;" :: "r"(mb), "r"(c) : "memory")
#define MBAR_EXPECT_TX(mb, n) asm volatile("mbarrier.arrive.expect_tx.shared.b64 _, [%0], %1;" :: "r"(mb), "r"(n) : "memory")
#define BULK_CP(dst, src, bytes, mbar) \
    asm volatile("cp.async.bulk.shared::cta.global.mbarrier::complete_tx::bytes [%0], [%1], %2, [%3];" \
        :: "r"(dst), "l"(src), "r"(bytes), "r"(mbar) : "memory")

#define MBAR_WAIT(mb, par) do { \
    uint32_t _m = (mb); uint32_t _p = (par); uint32_t _d; \
    asm volatile("{\n\t.reg .pred p;\n\t" \
        "mbarrier.try_wait.parity.acquire.cta.shared::cta.b64 p, [%1], %2;\n\t" \
        "selp.b32 %0, 1, 0, p;\n\t}" : "=r"(_d) : "r"(_m), "r"(_p) : "memory"); \
    if (!_d) { \
        asm volatile("{\n\t.reg .pred P1;\n\t" \
            "WL_%=:\n\t" \
            "mbarrier.try_wait.parity.acquire.cta.shared::cta.b64 P1, [%0], %1, 0x989680;\n\t" \
            "@P1 bra.uni WD_%=;\n\t" \
            "bra.uni WL_%=;\n\t" \
            "WD_%=:\n\t}" :: "r"(_m), "r"(_p) : "memory"); \
    } \
} while (0)

#define TC_LD_X32(r, ta) \
    asm volatile("tcgen05.ld.sync.aligned.32x32b.x32.b32 " \
        "{%0,%1,%2,%3,%4,%5,%6,%7,%8,%9,%10,%11,%12,%13,%14,%15," \
        "%16,%17,%18,%19,%20,%21,%22,%23,%24,%25,%26,%27,%28,%29,%30,%31}, [%32];" \
        : "=r"((r)[0]),"=r"((r)[1]),"=r"((r)[2]),"=r"((r)[3]),"=r"((r)[4]),"=r"((r)[5]),"=r"((r)[6]),"=r"((r)[7]), \
          "=r"((r)[8]),"=r"((r)[9]),"=r"((r)[10]),"=r"((r)[11]),"=r"((r)[12]),"=r"((r)[13]),"=r"((r)[14]),"=r"((r)[15]), \
          "=r"((r)[16]),"=r"((r)[17]),"=r"((r)[18]),"=r"((r)[19]),"=r"((r)[20]),"=r"((r)[21]),"=r"((r)[22]),"=r"((r)[23]), \
          "=r"((r)[24]),"=r"((r)[25]),"=r"((r)[26]),"=r"((r)[27]),"=r"((r)[28]),"=r"((r)[29]),"=r"((r)[30]),"=r"((r)[31]) \
        : "r"(ta))
#endif // HAS_TCGEN05

// idesc: dtype=F32(1<<4), atype=BF16(1<<7), btype=BF16(1<<10), N>>3 <<17, M>>4 <<24
#define IDESC_N128 0x8200490u
#define IDESC_N64  0x8100490u

// ---------------- smem layout (bytes), edge kernel ----------------
#define OFF_TMEM  0
#define OFF_MBAR0 16
#define OFF_MBAR1 24
#define OFF_MBT0  32      // TMA-full barriers
#define OFF_MBT1  40
#define OFF_SSEG  64       // 2 x 128 ints (ping-pong) = 1024B
#define OFF_BP2   1088     // 256 f
#define OFF_BP3   2112     // 64 f
#define OFF_BP1   2368     // 256 f
#define OFF_WP1   3392     // 1024 f
#define OFF_A0    8192     // 32KB: hi 16K + lo 16K
#define OFF_A1    40960
#define OFF_B0    73728    // 64KB: hi 32K + lo 32K   (h3T staging reuses this)
#define OFF_B1    139264
#define EDGE_SMEM 204800

#define NT_EDGE 256
#define NCTA_EDGE 148

// ---------------- weight prep: transpose + bf16 split into swizzled SMEM images ----------------
__global__ void prep_kernel(const float* __restrict__ Wp2, const float* __restrict__ Wp3) {
    int i = blockIdx.x * blockDim.x + threadIdx.x;
    char* w2h = (char*)g_W2S_hi;
    char* w2l = (char*)g_W2S_lo;
    char* w3h = (char*)g_W3S_hi;
    char* w3l = (char*)g_W3S_lo;
    if (i < 256 * 256) {
        int n = i >> 8, k = i & 255;
        float w = Wp2[k * 256 + n];
        __nv_bfloat16 h = __float2bfloat16(w);
        float r = w - __bfloat162float(h);
        const uint32_t off = (k >> 6) * 32768 + swz128(n * 128 + (k & 63) * 2);
        *(__nv_bfloat16*)(w2h + off) = h;
        *(__nv_bfloat16*)(w2l + off) = __float2bfloat16(r);
    }
    if (i < 64 * 256) {
        int n = i >> 8, k = i & 255;
        float w = Wp3[k * 64 + n];
        __nv_bfloat16 h = __float2bfloat16(w);
        float r = w - __bfloat162float(h);
        const uint32_t off = (k >> 6) * 8192 + swz128(n * 128 + (k & 63) * 2);
        *(__nv_bfloat16*)(w3h + off) = h;
        *(__nv_bfloat16*)(w3l + off) = __float2bfloat16(r);
    }
}

__global__ void zero_kernel() {
    const int i = blockIdx.x * blockDim.x + threadIdx.x;
    if (i < N_AG * AGG_STRIDE) g_agg[i] = 0.0f;
}

// barrier term + segmented-scan epilogue (h3T rows 0..63 must already be written)
__device__ __forceinline__ void do_epilogue(float* h3T, const int* ss, float px, float py, int tid) {
    if (tid < 128) {
        const float d = sqrtf(px * px + py * py);
        const float s = -1.0f / (d * (d - 0.18f));
        h3T[64 * 132 + tid] = px * s;
        h3T[65 * 132 + tid] = py * s;
    }
    __syncthreads();
    const int sc = (tid < 66) ? 0 : ((tid >= 128 && tid < 194) ? 1 : -1);
    if (sc >= 0) {
        const int col = (sc == 0) ? tid : (tid - 128);
        const int eb = sc * 64;
        const float* colp = h3T + col * 132 + eb;
        int cur = ss[eb];
        float run = 0.0f;
        #pragma unroll 4
        for (int e = 0; e < 64; e++) {
            const int sg = ss[eb + e];
            if (sg != cur) { atomicAdd(&g_agg[cur * 66 + col], run); run = 0.0f; cur = sg; }
            run += colp[e];
        }
        atomicAdd(&g_agg[cur * 66 + col], run);
    }
    __syncthreads();
}

// ---------------- edge kernel: persistent, fused MLP on tcgen05 + bulk-DMA weights ----------------
__global__ void __launch_bounds__(NT_EDGE, 1) edge_kernel(
    const float* __restrict__ ef, const int* __restrict__ seg,
    const float* __restrict__ Wp1, const float* __restrict__ bp1,
    const float* __restrict__ bp2, const float* __restrict__ bp3,
    const float* __restrict__ Wp2g, const float* __restrict__ Wp3g)
{
    extern __shared__ char sm[];
    const uint32_t smb = smem_u32(sm);
    const int tid = threadIdx.x;
    const int wid = tid >> 5;
    const int edge = tid & 127;     // each edge handled by 2 threads (col halves)
    const int half = tid >> 7;      // 0: cols [0,32), 1: cols [32,64) of each 64-chunk

    int*   sbuf = (int*)(sm + OFF_SSEG);       // 2 x 128
    float* bp2s = (float*)(sm + OFF_BP2);
    float* bp3s = (float*)(sm + OFF_BP3);
    float* bp1s = (float*)(sm + OFF_BP1);
    float* wp1s = (float*)(sm + OFF_WP1);
    float* h3T  = (float*)(sm + OFF_B0);       // [66][132] epilogue staging

#if HAS_TCGEN05
    if (wid == 0) { TC_ALLOC(smb + OFF_TMEM, 512); TC_RELINQ(); }
    if (tid == 0) {
        MBAR_INIT(smb + OFF_MBAR0, 1); MBAR_INIT(smb + OFF_MBAR1, 1);
        MBAR_INIT(smb + OFF_MBT0, 1);  MBAR_INIT(smb + OFF_MBT1, 1);
    }
#endif

    // invariants
    wp1s[tid] = Wp1[tid];             wp1s[tid + 256] = Wp1[tid + 256];
    wp1s[tid + 512] = Wp1[tid + 512]; wp1s[tid + 768] = Wp1[tid + 768];
    bp1s[tid] = bp1[tid];
    bp2s[tid] = bp2[tid];
    if (tid < 64) bp3s[tid] = bp3[tid];
    __syncthreads();

#if HAS_TCGEN05
    uint32_t tmem;
    asm volatile("ld.shared.b32 %0, [%1];" : "=r"(tmem) : "r"(smb + OFF_TMEM));
    const uint32_t tD2 = tmem;        // 256 cols
    const uint32_t tD3 = tmem + 256;  // 64 cols
    const uint32_t warp_off = (uint32_t)(wid & 3) << 21;
    int par0 = 0, par1 = 0, pend0 = 0, pend1 = 0;
    int pt0 = 0, pt1 = 0;   // TMA-full parities (only tid0 uses)

#define WAIT_BUF0() do { if (pend0) { MBAR_WAIT(smb + OFF_MBAR0, par0); par0 ^= 1; pend0 = 0; } } while (0)
#define WAIT_BUF1() do { if (pend1) { MBAR_WAIT(smb + OFF_MBAR1, par1); par1 ^= 1; pend1 = 0; } } while (0)

    const char* w2h = (const char*)g_W2S_hi;
    const char* w2l = (const char*)g_W2S_lo;
    const char* w3h = (const char*)g_W3S_hi;
    const char* w3l = (const char*)g_W3S_lo;

    float4 xcur = make_float4(0.f, 0.f, 0.f, 0.f), xprev;
    int cnt = 0;

    for (int tile = blockIdx.x; tile < NTILES; tile += gridDim.x, cnt++) {
        const int e0 = tile * 128;
        const int sb = cnt & 1;
        xprev = xcur;
        xcur = ((const float4*)ef)[e0 + edge];
        if (tid < 128) sbuf[sb * 128 + tid] = seg[e0 + tid];

        // ================= layer 2: K=256 in 4 chunks of 64 =================
        for (int kc = 0; kc < 4; kc++) {
            if (kc & 1) WAIT_BUF1(); else WAIT_BUF0();
            char* A = sm + ((kc & 1) ? OFF_A1 : OFF_A0);
            const uint32_t Bsm = smb + ((kc & 1) ? OFF_B1 : OFF_B0);
            const uint32_t mbt = smb + ((kc & 1) ? OFF_MBT1 : OFF_MBT0);

            // kick the weight DMA for this chunk (hi 32K + lo 32K)
            if (tid == 0) {
                MBAR_EXPECT_TX(mbt, 65536);
                BULK_CP(Bsm,         w2h + kc * 32768, 32768, mbt);
                BULK_CP(Bsm + 32768, w2l + kc * 32768, 32768, mbt);
            }

            // layer 1 on the fly: this thread does 32 of the 64 chunk cols
            #pragma unroll
            for (int g = 0; g < 4; g++) {
                const int gg = half * 4 + g;
                uint32_t hi4[4], lo4[4];
                #pragma unroll
                for (int q = 0; q < 4; q++) {
                    const int c = kc * 64 + gg * 8 + q * 2;
                    float v0 = fmaf(xcur.x, wp1s[c],       fmaf(xcur.y, wp1s[256 + c],
                               fmaf(xcur.z, wp1s[512 + c], fmaf(xcur.w, wp1s[768 + c], bp1s[c]))));
                    float v1 = fmaf(xcur.x, wp1s[c + 1],       fmaf(xcur.y, wp1s[256 + c + 1],
                               fmaf(xcur.z, wp1s[512 + c + 1], fmaf(xcur.w, wp1s[768 + c + 1], bp1s[c + 1]))));
                    v0 = fmaxf(v0, 0.0f); v1 = fmaxf(v1, 0.0f);
                    split2(v0, v1, hi4[q], lo4[q]);
                }
                const uint32_t so = swz128(edge * 128 + gg * 16);
                *(uint4*)(A + so)         = make_uint4(hi4[0], hi4[1], hi4[2], hi4[3]);
                *(uint4*)(A + 16384 + so) = make_uint4(lo4[0], lo4[1], lo4[2], lo4[3]);
            }
            FENCE_ASYNC();
            __syncthreads();

            if (tid == 0) {
                // wait weight DMA landed
                if (kc & 1) { MBAR_WAIT(mbt, pt1); pt1 ^= 1; }
                else        { MBAR_WAIT(mbt, pt0); pt0 ^= 1; }
                const uint64_t dAh = mk_desc(smb + (uint32_t)(A - sm));
                const uint64_t dAl = dAh + 1024;   // +16KB
                const uint64_t dBh = mk_desc(Bsm);
                const uint64_t dBl = dBh + 2048;   // +32KB
                #pragma unroll
                for (int s = 0; s < 4; s++) {
                    #pragma unroll
                    for (int h = 0; h < 2; h++) {
                        const uint32_t d = tD2 + h * 128;
                        const uint64_t bo = (uint64_t)h * 1024 + s * 2;
                        mma_f16_ss(d, dAh + s * 2, dBh + bo, IDESC_N128, !(kc == 0 && s == 0));
                        mma_f16_ss(d, dAh + s * 2, dBl + bo, IDESC_N128, 1);
                        mma_f16_ss(d, dAl + s * 2, dBh + bo, IDESC_N128, 1);
                    }
                }
                TC_COMMIT(smb + ((kc & 1) ? OFF_MBAR1 : OFF_MBAR0));
            }
            if (kc & 1) pend1 = 1; else pend0 = 1;
        }

        // drain layer-2 MMAs (required before reading D2)
        WAIT_BUF0();
        WAIT_BUF1();
        TC_FENCE_AFTER();

        // -------- epilogue of PREVIOUS tile fills the drain bubble --------
        if (cnt > 0) {
            uint32_t r0[32];
            TC_LD_X32(r0, tD3 + half * 32 + warp_off);
            TC_WAIT_LD();
            TC_FENCE_BEFORE();
            #pragma unroll
            for (int c = 0; c < 32; c++)
                h3T[(half * 32 + c) * 132 + edge] = __uint_as_float(r0[c]) + bp3s[half * 32 + c];
            do_epilogue(h3T, sbuf + (sb ^ 1) * 128, xprev.x, xprev.y, tid);
        }

        // ================= layer 3: h2 slices -> D3 =================
        for (int i = 0; i < 4; i++) {
            if (i & 1) WAIT_BUF1(); else WAIT_BUF0();

            const uint32_t B3sm = smb + OFF_B1 + (i & 1) * 16384;   // hi 8K + lo 8K
            const uint32_t mbt = smb + ((i & 1) ? OFF_MBT1 : OFF_MBT0);
            if (tid == 0) {
                MBAR_EXPECT_TX(mbt, 16384);
                BULK_CP(B3sm,        w3h + i * 8192, 8192, mbt);
                BULK_CP(B3sm + 8192, w3l + i * 8192, 8192, mbt);
            }

            uint32_t r0[32];
            TC_LD_X32(r0, tD2 + i * 64 + half * 32 + warp_off);
            TC_WAIT_LD();

            char* A2 = sm + ((i & 1) ? OFF_A1 : OFF_A0);

            #pragma unroll
            for (int g = 0; g < 4; g++) {
                const int gg = half * 4 + g;
                uint32_t hi4[4], lo4[4];
                #pragma unroll
                for (int q = 0; q < 4; q++) {
                    const int j = g * 8 + q * 2;
                    const int c = i * 64 + half * 32 + j;
                    float v0 = fmaxf(__uint_as_float(r0[j])     + bp2s[c],     0.0f);
                    float v1 = fmaxf(__uint_as_float(r0[j + 1]) + bp2s[c + 1], 0.0f);
                    split2(v0, v1, hi4[q], lo4[q]);
                }
                const uint32_t so = swz128(edge * 128 + gg * 16);
                *(uint4*)(A2 + so)         = make_uint4(hi4[0], hi4[1], hi4[2], hi4[3]);
                *(uint4*)(A2 + 16384 + so) = make_uint4(lo4[0], lo4[1], lo4[2], lo4[3]);
            }
            FENCE_ASYNC();
            TC_FENCE_BEFORE();
            __syncthreads();

            if (tid == 0) {
                TC_FENCE_AFTER();
                if (i & 1) { MBAR_WAIT(mbt, pt1); pt1 ^= 1; }
                else       { MBAR_WAIT(mbt, pt0); pt0 ^= 1; }
                const uint64_t dAh = mk_desc(smb + (uint32_t)(A2 - sm));
                const uint64_t dAl = dAh + 1024;  // +16KB
                const uint64_t dBh = mk_desc(B3sm);
                const uint64_t dBl = dBh + 512;   // +8KB
                #pragma unroll
                for (int s = 0; s < 4; s++) {
                    mma_f16_ss(tD3, dAh + s * 2, dBh + s * 2, IDESC_N64, !(i == 0 && s == 0));
                    mma_f16_ss(tD3, dAh + s * 2, dBl + s * 2, IDESC_N64, 1);
                    mma_f16_ss(tD3, dAl + s * 2, dBh + s * 2, IDESC_N64, 1);
                }
                TC_COMMIT(smb + ((i & 1) ? OFF_MBAR1 : OFF_MBAR0));
            }
            if (i & 1) pend1 = 1; else pend0 = 1;
        }
    }

    // -------- final drain + epilogue of the last tile --------
    WAIT_BUF0();
    WAIT_BUF1();
    if (cnt > 0) {
        TC_FENCE_AFTER();
        uint32_t r0[32];
        TC_LD_X32(r0, tD3 + half * 32 + warp_off);
        TC_WAIT_LD();
        TC_FENCE_BEFORE();
        #pragma unroll
        for (int c = 0; c < 32; c++)
            h3T[(half * 32 + c) * 132 + edge] = __uint_as_float(r0[c]) + bp3s[half * 32 + c];
        do_epilogue(h3T, sbuf + ((cnt - 1) & 1) * 128, xcur.x, xcur.y, tid);
    }
    __syncthreads();
    if (wid == 0) TC_DEALLOC(tmem, 512);
#undef WAIT_BUF0
#undef WAIT_BUF1
#else
    // ---------- correct scalar fallback (compiled only for non-'a' targets) ----------
    for (int tile = blockIdx.x; tile < NTILES; tile += gridDim.x) {
        const int e0 = tile * 128;
        const float4 x = ((const float4*)ef)[e0 + edge];
        if (tid < 128) sbuf[tid] = seg[e0 + tid];
        __syncthreads();
        if (tid < 128) {
            float* hbuf = (float*)(sm + OFF_A0);   // [256][128] k-major
            for (int k = 0; k < 256; k++) {
                float v = fmaf(x.x, wp1s[k],       fmaf(x.y, wp1s[256 + k],
                          fmaf(x.z, wp1s[512 + k], fmaf(x.w, wp1s[768 + k], bp1s[k]))));
                hbuf[k * 128 + tid] = fmaxf(v, 0.0f);
            }
            float h3a[64];
            for (int n = 0; n < 64; n++) h3a[n] = bp3s[n];
            for (int kc = 0; kc < 4; kc++) {
                float h2c[64];
                for (int j = 0; j < 64; j++) {
                    const int c = kc * 64 + j;
                    float s = bp2s[c];
                    for (int k = 0; k < 256; k++)
                        s = fmaf(hbuf[k * 128 + tid], Wp2g[k * 256 + c], s);
                    h2c[j] = fmaxf(s, 0.0f);
                }
                for (int j = 0; j < 64; j++) {
                    const int r = kc * 64 + j;
                    for (int n = 0; n < 64; n++)
                        h3a[n] = fmaf(h2c[j], Wp3g[r * 64 + n], h3a[n]);
                }
            }
            for (int c = 0; c < 64; c++)
                h3T[c * 132 + tid] = h3a[c];
        }
        __syncthreads();
        do_epilogue(h3T, sbuf, x.x, x.y, tid);
        __syncthreads();
    }
#endif
}

// ---------------- agent kernel (fp32x2 path, arch-portable) ----------------
__device__ __forceinline__ unsigned long long dup2(float a) {
    unsigned long long r;
    asm("mov.b64 %0, {%1, %1};" : "=l"(r) : "f"(a));
    return r;
}
__device__ __forceinline__ unsigned long long pack2(float lo, float hi) {
    unsigned long long r;
    asm("mov.b64 %0, {%1, %2};" : "=l"(r) : "f"(lo), "f"(hi));
    return r;
}
__device__ __forceinline__ void unpack2(unsigned long long v, float& lo, float& hi) {
    asm("mov.b64 {%0, %1}, %2;" : "=f"(lo), "=f"(hi) : "l"(v));
}
__device__ __forceinline__ void fma2(unsigned long long& acc, unsigned long long a, unsigned long long b) {
    asm("fma.rn.f32x2 %0, %1, %2, %0;" : "+l"(acc) : "l"(a), "l"(b));
}

#define AGENT_SMEM_FLOATS (2112 + 8448 + 8448 + 8192 + 512)
#define AGENT_SMEM_BYTES  (AGENT_SMEM_FLOATS * 4)

__global__ void __launch_bounds__(256, 2) agent_kernel(
    const float* __restrict__ Wr1, const float* __restrict__ br1,
    const float* __restrict__ Wr2, const float* __restrict__ br2,
    const float* __restrict__ Wr3, const float* __restrict__ br3,
    float* __restrict__ out)
{
    extern __shared__ float smf[];
    float* g1 = smf;
    float* h2 = g1 + 2112;
    float* r2 = h2 + 8448;
    float* wc = r2 + 8448;
    float* w3 = wc + 8192;

    const int tid = threadIdx.x;
    const int a0 = blockIdx.x * 32;

    #pragma unroll
    for (int i = 0; i < 8; i++) {
        const int idx = tid + i * 256;
        const int e = idx >> 6, k = idx & 63;
        g1[k * 33 + e] = g_agg[(a0 + e) * 66 + k];
    }
    w3[tid] = Wr3[tid];
    w3[tid + 256] = Wr3[tid + 256];
    __syncthreads();

    const int te = tid & 7;
    const int tn = tid >> 3;
    const int el = te * 4;
    const int n0 = tn * 8;

    unsigned long long acc[4][4];

    {   // r1 = relu(agg @ Wr1 + br1), K=64
        const float4 blo = *(const float4*)&br1[n0];
        const float4 bhi = *(const float4*)&br1[n0 + 4];
        const unsigned long long q0 = pack2(blo.x, blo.y), q1 = pack2(blo.z, blo.w);
        const unsigned long long q2 = pack2(bhi.x, bhi.y), q3 = pack2(bhi.z, bhi.w);
        #pragma unroll
        for (int i = 0; i < 4; i++) { acc[i][0]=q0; acc[i][1]=q1; acc[i][2]=q2; acc[i][3]=q3; }

        for (int kc = 0; kc < 2; kc++) {
            __syncthreads();
            const float4* src = (const float4*)(Wr1 + kc * 32 * 256);
            float4* dst = (float4*)wc;
            #pragma unroll
            for (int i = 0; i < 8; i++) dst[tid + i * 256] = src[tid + i * 256];
            __syncthreads();
            #pragma unroll
            for (int k = 0; k < 32; k++) {
                const float* hrow = &g1[(kc * 32 + k) * 33 + el];
                const unsigned long long a0d = dup2(hrow[0]);
                const unsigned long long a1d = dup2(hrow[1]);
                const unsigned long long a2d = dup2(hrow[2]);
                const unsigned long long a3d = dup2(hrow[3]);
                const ulonglong2 u0 = *(const ulonglong2*)&wc[k * 256 + n0];
                const ulonglong2 u1 = *(const ulonglong2*)&wc[k * 256 + n0 + 4];
                fma2(acc[0][0], a0d, u0.x); fma2(acc[0][1], a0d, u0.y);
                fma2(acc[0][2], a0d, u1.x); fma2(acc[0][3], a0d, u1.y);
                fma2(acc[1][0], a1d, u0.x); fma2(acc[1][1], a1d, u0.y);
                fma2(acc[1][2], a1d, u1.x); fma2(acc[1][3], a1d, u1.y);
                fma2(acc[2][0], a2d, u0.x); fma2(acc[2][1], a2d, u0.y);
                fma2(acc[2][2], a2d, u1.x); fma2(acc[2][3], a2d, u1.y);
                fma2(acc[3][0], a3d, u0.x); fma2(acc[3][1], a3d, u0.y);
                fma2(acc[3][2], a3d, u1.x); fma2(acc[3][3], a3d, u1.y);
            }
        }
        #pragma unroll
        for (int i = 0; i < 4; i++)
            #pragma unroll
            for (int j = 0; j < 4; j++) {
                float lo, hi; unpack2(acc[i][j], lo, hi);
                h2[(n0 + 2*j    ) * 33 + el + i] = fmaxf(lo, 0.0f);
                h2[(n0 + 2*j + 1) * 33 + el + i] = fmaxf(hi, 0.0f);
            }
    }

    {   // r2 = relu(r1 @ Wr2 + br2), K=256
        const float4 blo = *(const float4*)&br2[n0];
        const float4 bhi = *(const float4*)&br2[n0 + 4];
        const unsigned long long q0 = pack2(blo.x, blo.y), q1 = pack2(blo.z, blo.w);
        const unsigned long long q2 = pack2(bhi.x, bhi.y), q3 = pack2(bhi.z, bhi.w);
        #pragma unroll
        for (int i = 0; i < 4; i++) { acc[i][0]=q0; acc[i][1]=q1; acc[i][2]=q2; acc[i][3]=q3; }

        for (int kc = 0; kc < 8; kc++) {
            __syncthreads();
            const float4* src = (const float4*)(Wr2 + kc * 32 * 256);
            float4* dst = (float4*)wc;
            #pragma unroll
            for (int i = 0; i < 8; i++) dst[tid + i * 256] = src[tid + i * 256];
            __syncthreads();
            #pragma unroll
            for (int k = 0; k < 32; k++) {
                const float* hrow = &h2[(kc * 32 + k) * 33 + el];
                const unsigned long long a0d = dup2(hrow[0]);
                const unsigned long long a1d = dup2(hrow[1]);
                const unsigned long long a2d = dup2(hrow[2]);
                const unsigned long long a3d = dup2(hrow[3]);
                const ulonglong2 u0 = *(const ulonglong2*)&wc[k * 256 + n0];
                const ulonglong2 u1 = *(const ulonglong2*)&wc[k * 256 + n0 + 4];
                fma2(acc[0][0], a0d, u0.x); fma2(acc[0][1], a0d, u0.y);
                fma2(acc[0][2], a0d, u1.x); fma2(acc[0][3], a0d, u1.y);
                fma2(acc[1][0], a1d, u0.x); fma2(acc[1][1], a1d, u0.y);
                fma2(acc[1][2], a1d, u1.x); fma2(acc[1][3], a1d, u1.y);
                fma2(acc[2][0], a2d, u0.x); fma2(acc[2][1], a2d, u0.y);
                fma2(acc[2][2], a2d, u1.x); fma2(acc[2][3], a2d, u1.y);
                fma2(acc[3][0], a3d, u0.x); fma2(acc[3][1], a3d, u0.y);
                fma2(acc[3][2], a3d, u1.x); fma2(acc[3][3], a3d, u1.y);
            }
        }
        #pragma unroll
        for (int i = 0; i < 4; i++)
            #pragma unroll
            for (int j = 0; j < 4; j++) {
                float lo, hi; unpack2(acc[i][j], lo, hi);
                r2[(n0 + 2*j    ) * 33 + el + i] = fmaxf(lo, 0.0f);
                r2[(n0 + 2*j + 1) * 33 + el + i] = fmaxf(hi, 0.0f);
            }
    }
    __syncthreads();

    if (tid < 64) {
        const int e = tid >> 1, c = tid & 1;
        float sum = br3[c];
        #pragma unroll 8
        for (int k = 0; k < 256; k++)
            sum += r2[k * 33 + e] * w3[k * 2 + c];
        out[(a0 + e) * 2 + c] = sum + g_agg[(a0 + e) * 66 + 64 + c];
    }
}

// ---------------- launch ----------------
extern "C" void kernel_launch(void* const* d_in, const int* in_sizes, int n_in,
                              void* d_out, int out_size) {
    const float* ef  = (const float*)d_in[0];
    const int*   seg = (const int*)  d_in[1];
    const float* Wp1 = (const float*)d_in[2];
    const float* bp1 = (const float*)d_in[3];
    const float* Wp2 = (const float*)d_in[4];
    const float* bp2 = (const float*)d_in[5];
    const float* Wp3 = (const float*)d_in[6];
    const float* bp3 = (const float*)d_in[7];
    const float* Wr1 = (const float*)d_in[8];
    const float* br1 = (const float*)d_in[9];
    const float* Wr2 = (const float*)d_in[10];
    const float* br2 = (const float*)d_in[11];
    const float* Wr3 = (const float*)d_in[12];
    const float* br3 = (const float*)d_in[13];
    float* out = (float*)d_out;

    cudaFuncSetAttribute(edge_kernel,  cudaFuncAttributeMaxDynamicSharedMemorySize, EDGE_SMEM);
    cudaFuncSetAttribute(agent_kernel, cudaFuncAttributeMaxDynamicSharedMemorySize, AGENT_SMEM_BYTES);

    prep_kernel<<<256, 256>>>(Wp2, Wp3);
    zero_kernel<<<(N_AG * AGG_STRIDE + 255) / 256, 256>>>();
    edge_kernel<<<NCTA_EDGE, NT_EDGE, EDGE_SMEM>>>(ef, seg, Wp1, bp1, bp2, bp3, Wp2, Wp3);
    agent_kernel<<<N_AG / 32, 256, AGENT_SMEM_BYTES>>>(Wr1, br1, Wr2, br2, Wr3, br3, out);
}